// round 6
// baseline (speedup 1.0000x reference)
#include <cuda_runtime.h>
#include <math.h>

#define TILE 16
#define NTHREADS 128
#define NMAX 50000
#define EMAX 600000

typedef unsigned long long u64;

// ---------------- device scratch (no allocations allowed) ----------------
__device__ float g_q[NMAX * 128];      // q = MLP_q(h)
__device__ float g_kHd[NMAX * 128];    // h @ kW1[24:152]
__device__ float g_kHs[NMAX * 128];    // h @ kW1[152:280]
__device__ float g_vHd[NMAX * 128];    // h @ vW1[24:152]
__device__ float g_vHs[NMAX * 128];    // h @ vW1[152:280]
__device__ float g_attn[NMAX * 128];   // segment-summed alpha*v
__device__ float g_mx[NMAX * 16];      // per-(node,head) running max
__device__ float g_den[NMAX * 16];     // per-(node,head) exp-sum
__device__ float g_scores[EMAX * 16];  // scores, then exp(scores-max) in place

// ---------------- packed f32x2 helpers (Blackwell FFMA2 — PTX only) ----------------
__device__ __forceinline__ u64 fma2(u64 a, u64 b, u64 c) {
    u64 d;
    asm("fma.rn.f32x2 %0, %1, %2, %3;" : "=l"(d) : "l"(a), "l"(b), "l"(c));
    return d;
}
__device__ __forceinline__ u64 pack2(float lo, float hi) {
    u64 r;
    asm("mov.b64 %0, {%1, %2};" : "=l"(r) : "f"(lo), "f"(hi));
    return r;
}
__device__ __forceinline__ float hsum2(u64 a) {
    float x, y;
    asm("mov.b64 {%0, %1}, %2;" : "=f"(x), "=f"(y) : "l"(a));
    return x + y;
}

// monotone float atomic max via signed/unsigned int tricks (init to -inf)
__device__ __forceinline__ void atomicMaxF(float* addr, float v) {
    if (v >= 0.f) atomicMax((int*)addr, __float_as_int(v));
    else          atomicMin((unsigned int*)addr, __float_as_uint(v));
}

// ---------------- LN(+affine)+ReLU over hid_s rows ----------------
template <int TE>
__device__ __forceinline__ void ln_relu(float* hid_s, float* mu_s, float* rs_s,
                                        const float* __restrict__ gam,
                                        const float* __restrict__ bet) {
    const int t = threadIdx.x;
    const int w = t >> 5, lane = t & 31;
    __syncthreads();
    for (int e = w; e < TE; e += 4) {
        float s = 0.f, s2 = 0.f;
#pragma unroll
        for (int j = 0; j < 4; j++) {
            const float v = hid_s[e * 128 + lane + j * 32];
            s += v; s2 += v * v;
        }
#pragma unroll
        for (int o = 16; o; o >>= 1) {
            s  += __shfl_down_sync(0xffffffffu, s, o);
            s2 += __shfl_down_sync(0xffffffffu, s2, o);
        }
        if (lane == 0) {
            const float mu = s * (1.f / 128.f);
            const float var = s2 * (1.f / 128.f) - mu * mu;
            mu_s[e] = mu;
            rs_s[e] = rsqrtf(var + 1e-5f);
        }
    }
    __syncthreads();
    const float gt = gam[t], bt = bet[t];
#pragma unroll
    for (int e = 0; e < TE; e++) {
        float v = hid_s[e * 128 + t];
        v = fmaf((v - mu_s[e]) * rs_s[e], gt, bt);
        hid_s[e * 128 + t] = fmaxf(v, 0.f);
    }
    __syncthreads();
}

// second linear 128 -> 128 via FFMA2, thread t owns column t
template <int TE>
__device__ __forceinline__ void lin2(const float* hid_s,
                                     const float* __restrict__ W2,
                                     const float* __restrict__ b2, float* out) {
    const int t = threadIdx.x;
    u64 acc[TE];
    {
        const u64 z = pack2(b2[t], 0.f);
#pragma unroll
        for (int e = 0; e < TE; e++) acc[e] = z;
    }
    for (int i = 0; i < 128; i += 4) {
        const u64 wp0 = pack2(W2[(i + 0) * 128 + t], W2[(i + 1) * 128 + t]);
        const u64 wp1 = pack2(W2[(i + 2) * 128 + t], W2[(i + 3) * 128 + t]);
#pragma unroll
        for (int e = 0; e < TE; e++) {
            const ulonglong2 x = *(const ulonglong2*)(hid_s + e * 128 + i);
            acc[e] = fma2(x.x, wp0, acc[e]);
            acc[e] = fma2(x.y, wp1, acc[e]);
        }
    }
#pragma unroll
    for (int e = 0; e < TE; e++) out[e] = hsum2(acc[e]);
}

// full MLP for node kernels (first linear from shared input, FFMA2)
template <int KIN, int TE>
__device__ __forceinline__ void mlp_tile(
    const float* in_s, float* hid_s, float* mu_s, float* rs_s,
    const float* __restrict__ W1, const float* __restrict__ b1,
    const float* __restrict__ gam, const float* __restrict__ bet,
    const float* __restrict__ W2, const float* __restrict__ b2, float* out) {
    const int t = threadIdx.x;
    u64 acc[TE];
    {
        const u64 z = pack2(b1[t], 0.f);
#pragma unroll
        for (int e = 0; e < TE; e++) acc[e] = z;
    }
    for (int i = 0; i < KIN; i += 4) {
        const u64 wp0 = pack2(W1[(i + 0) * 128 + t], W1[(i + 1) * 128 + t]);
        const u64 wp1 = pack2(W1[(i + 2) * 128 + t], W1[(i + 3) * 128 + t]);
#pragma unroll
        for (int e = 0; e < TE; e++) {
            const ulonglong2 x = *(const ulonglong2*)(in_s + e * KIN + i);
            acc[e] = fma2(x.x, wp0, acc[e]);
            acc[e] = fma2(x.y, wp1, acc[e]);
        }
    }
#pragma unroll
    for (int e = 0; e < TE; e++) hid_s[e * 128 + t] = hsum2(acc[e]);
    ln_relu<TE>(hid_s, mu_s, rs_s, gam, bet);
    lin2<TE>(hid_s, W2, b2, out);
    __syncthreads();
}

// 128->128 projection (no bias) via FFMA2: acc[e] = in_s[e]@W
template <int TE>
__device__ __forceinline__ void proj_tile(const float* in_s,
                                          const float* __restrict__ W,
                                          float* outv) {
    const int t = threadIdx.x;
    u64 acc[TE];
#pragma unroll
    for (int e = 0; e < TE; e++) acc[e] = 0ull;
    for (int i = 0; i < 128; i += 4) {
        const u64 wp0 = pack2(W[(i + 0) * 128 + t], W[(i + 1) * 128 + t]);
        const u64 wp1 = pack2(W[(i + 2) * 128 + t], W[(i + 3) * 128 + t]);
#pragma unroll
        for (int e = 0; e < TE; e++) {
            const ulonglong2 x = *(const ulonglong2*)(in_s + e * 128 + i);
            acc[e] = fma2(x.x, wp0, acc[e]);
            acc[e] = fma2(x.y, wp1, acc[e]);
        }
    }
#pragma unroll
    for (int e = 0; e < TE; e++) outv[e] = hsum2(acc[e]);
}

// ---------------- kernels ----------------
__global__ void init_kernel(int n) {
    const int i = blockIdx.x * blockDim.x + threadIdx.x;
    if (i < n * 128) g_attn[i] = 0.f;
    if (i < n * 16) { g_mx[i] = __int_as_float(0xff800000); g_den[i] = 0.f; }
}

// node prep: q MLP + 4 projections (kHd,kHs,vHd,vHs)
__global__ void __launch_bounds__(NTHREADS)
nodeprep_kernel(const float* __restrict__ h, int n,
                const float* qW1, const float* qb1, const float* qg,
                const float* qbe, const float* qW2, const float* qb2,
                const float* kW1, const float* vW1) {
    __shared__ __align__(16) float in_s[TILE * 128];
    __shared__ __align__(16) float hid_s[TILE * 128];
    __shared__ float mu_s[TILE], rs_s[TILE];
    const int t = threadIdx.x;
    const int n0 = blockIdx.x * TILE;
    const int ne = min(TILE, n - n0);
    for (int e = 0; e < ne; e++) in_s[e * 128 + t] = h[(n0 + e) * 128 + t];
    __syncthreads();

    float out[TILE];
    mlp_tile<128, TILE>(in_s, hid_s, mu_s, rs_s, qW1, qb1, qg, qbe, qW2, qb2, out);
    for (int e = 0; e < ne; e++) g_q[(n0 + e) * 128 + t] = out[e];

    proj_tile<TILE>(in_s, kW1 + 24 * 128, out);
    for (int e = 0; e < ne; e++) g_kHd[(n0 + e) * 128 + t] = out[e];
    proj_tile<TILE>(in_s, kW1 + 152 * 128, out);
    for (int e = 0; e < ne; e++) g_kHs[(n0 + e) * 128 + t] = out[e];
    proj_tile<TILE>(in_s, vW1 + 24 * 128, out);
    for (int e = 0; e < ne; e++) g_vHd[(n0 + e) * 128 + t] = out[e];
    proj_tile<TILE>(in_s, vW1 + 152 * 128, out);
    for (int e = 0; e < ne; e++) g_vHs[(n0 + e) * 128 + t] = out[e];
}

// edge pass A: k-MLP via gather-add + small GEMM, scores + atomicMax
__global__ void __launch_bounds__(NTHREADS)
edgeA_kernel(const float* __restrict__ rf, const float* __restrict__ ef,
             const int* __restrict__ srcI, const int* __restrict__ dstI, int Ecnt,
             const float* kW1, const float* kb1, const float* kg,
             const float* kbe, const float* kW2, const float* kb2) {
    __shared__ __align__(16) float sm_in[TILE * 24];
    __shared__ __align__(16) float hid_s[TILE * 128];
    __shared__ float mu_s[TILE], rs_s[TILE];
    __shared__ int dst_s[TILE], src_s[TILE];
    const int t = threadIdx.x;
    const int e0 = blockIdx.x * TILE;
    const int ne = min(TILE, Ecnt - e0);

    if (t < ne) { dst_s[t] = dstI[e0 + t]; src_s[t] = srcI[e0 + t]; }
    for (int j = t; j < ne * 24; j += NTHREADS) {
        const int e = j / 24, i = j % 24;
        sm_in[e * 24 + i] = (i < 4) ? ef[(e0 + e) * 4 + i] : rf[(e0 + e) * 20 + (i - 4)];
    }
    __syncthreads();

    // first layer: bias + gathered node projections + small GEMM over 24 dims
    float acc[TILE];
    const float bb1 = kb1[t];
#pragma unroll
    for (int e = 0; e < TILE; e++) {
        if (e < ne)
            acc[e] = bb1 + g_kHd[dst_s[e] * 128 + t] + g_kHs[src_s[e] * 128 + t];
        else acc[e] = 0.f;
    }
    for (int i = 0; i < 24; i += 4) {
        const float w0 = kW1[(i + 0) * 128 + t];
        const float w1 = kW1[(i + 1) * 128 + t];
        const float w2 = kW1[(i + 2) * 128 + t];
        const float w3 = kW1[(i + 3) * 128 + t];
#pragma unroll
        for (int e = 0; e < TILE; e++) {
            const float4 x = *(const float4*)(sm_in + e * 24 + i);
            acc[e] = fmaf(x.x, w0, acc[e]);
            acc[e] = fmaf(x.y, w1, acc[e]);
            acc[e] = fmaf(x.z, w2, acc[e]);
            acc[e] = fmaf(x.w, w3, acc[e]);
        }
    }
#pragma unroll
    for (int e = 0; e < TILE; e++) hid_s[e * 128 + t] = acc[e];
    ln_relu<TILE>(hid_s, mu_s, rs_s, kg, kbe);
    float kout[TILE];
    lin2<TILE>(hid_s, kW2, kb2, kout);

    // per-head scores vs q[dst]
    for (int e = 0; e < ne; e++) {
        float val = kout[e] * g_q[dst_s[e] * 128 + t];
        val += __shfl_down_sync(0xffffffffu, val, 4, 8);
        val += __shfl_down_sync(0xffffffffu, val, 2, 8);
        val += __shfl_down_sync(0xffffffffu, val, 1, 8);
        if ((t & 7) == 0) {
            const float sc = val * 0.35355339059327373f; // 1/sqrt(8)
            g_scores[(e0 + e) * 16 + (t >> 3)] = sc;
            atomicMaxF(&g_mx[dst_s[e] * 16 + (t >> 3)], sc);
        }
    }
}

__global__ void softmax_kernel(const int* __restrict__ dstI, int Ecnt) {
    const int gid = blockIdx.x * blockDim.x + threadIdx.x;
    if (gid >= Ecnt * 16) return;
    const int e = gid >> 4, hh = gid & 15;
    const int node = dstI[e];
    const float exv = expf(g_scores[gid] - g_mx[node * 16 + hh]);
    g_scores[gid] = exv;
    atomicAdd(&g_den[node * 16 + hh], exv);
}

// edge pass B: v-MLP via gather-add + fused alpha*v scatter
__global__ void __launch_bounds__(NTHREADS)
edgeB_kernel(const float* __restrict__ rf, const float* __restrict__ ef,
             const float* __restrict__ ew,
             const int* __restrict__ srcI, const int* __restrict__ dstI, int Ecnt,
             const float* vW1, const float* vb1, const float* vg,
             const float* vbe, const float* vW2, const float* vb2) {
    __shared__ __align__(16) float sm_in[TILE * 24];
    __shared__ __align__(16) float hid_s[TILE * 128];
    __shared__ float mu_s[TILE], rs_s[TILE], ew_s[TILE];
    __shared__ int dst_s[TILE], src_s[TILE];
    const int t = threadIdx.x;
    const int e0 = blockIdx.x * TILE;
    const int ne = min(TILE, Ecnt - e0);

    if (t < ne) {
        dst_s[t] = dstI[e0 + t];
        src_s[t] = srcI[e0 + t];
        ew_s[t] = ew[e0 + t];
    }
    for (int j = t; j < ne * 24; j += NTHREADS) {
        const int e = j / 24, i = j % 24;
        sm_in[e * 24 + i] = (i < 4) ? ef[(e0 + e) * 4 + i] : rf[(e0 + e) * 20 + (i - 4)];
    }
    __syncthreads();

    float acc[TILE];
    const float bb1 = vb1[t];
#pragma unroll
    for (int e = 0; e < TILE; e++) {
        if (e < ne)
            acc[e] = bb1 + g_vHd[dst_s[e] * 128 + t] + g_vHs[src_s[e] * 128 + t];
        else acc[e] = 0.f;
    }
    for (int i = 0; i < 24; i += 4) {
        const float w0 = vW1[(i + 0) * 128 + t];
        const float w1 = vW1[(i + 1) * 128 + t];
        const float w2 = vW1[(i + 2) * 128 + t];
        const float w3 = vW1[(i + 3) * 128 + t];
#pragma unroll
        for (int e = 0; e < TILE; e++) {
            const float4 x = *(const float4*)(sm_in + e * 24 + i);
            acc[e] = fmaf(x.x, w0, acc[e]);
            acc[e] = fmaf(x.y, w1, acc[e]);
            acc[e] = fmaf(x.z, w2, acc[e]);
            acc[e] = fmaf(x.w, w3, acc[e]);
        }
    }
#pragma unroll
    for (int e = 0; e < TILE; e++) hid_s[e * 128 + t] = acc[e];
    ln_relu<TILE>(hid_s, mu_s, rs_s, vg, vbe);
    float vout[TILE];
    lin2<TILE>(hid_s, vW2, vb2, vout);

    // alpha * v * e_w, scattered to destination node
    const int hh = t >> 3;
    for (int e = 0; e < ne; e++) {
        const int dd = dst_s[e];
        const float alpha = g_scores[(e0 + e) * 16 + hh] / g_den[dd * 16 + hh];
        atomicAdd(&g_attn[dd * 128 + t], vout[e] * ew_s[e] * alpha);
    }
}

__global__ void __launch_bounds__(NTHREADS)
out_kernel(const float* __restrict__ h, float* __restrict__ outp, int n,
           const float* W1, const float* b1, const float* gam,
           const float* bet, const float* W2, const float* b2) {
    __shared__ __align__(16) float in_s[TILE * 256];
    __shared__ __align__(16) float hid_s[TILE * 128];
    __shared__ float mu_s[TILE], rs_s[TILE];
    const int t = threadIdx.x;
    const int n0 = blockIdx.x * TILE;
    const int ne = min(TILE, n - n0);
    for (int e = 0; e < ne; e++) {
        const int node = n0 + e;
        in_s[e * 256 + t] = g_attn[node * 128 + t];
        in_s[e * 256 + 128 + t] = h[node * 128 + t];
    }
    __syncthreads();
    float out[TILE];
    mlp_tile<256, TILE>(in_s, hid_s, mu_s, rs_s, W1, b1, gam, bet, W2, b2, out);
    for (int e = 0; e < ne; e++) outp[(n0 + e) * 128 + t] = out[e];
}

// ---------------- launch ----------------
extern "C" void kernel_launch(void* const* d_in, const int* in_sizes, int n_in,
                              void* d_out, int out_size) {
    int ih = -1, ir = -1, ief = -1, iei = -1, iew = -1, xk0 = -1;
    for (int i = 0; i < n_in; i++) {
        switch (in_sizes[i]) {
            case 6400000:  if (ih  < 0) ih  = i; break; // h [N,128]
            case 12000000: if (ir  < 0) ir  = i; break; // r_feat [E,20]
            case 2400000:  if (ief < 0) ief = i; break; // edge_feat [E,4]
            case 1200000:  if (iei < 0) iei = i; break; // edge_index [2,E]
            case 600000:   if (iew < 0) iew = i; break; // e_w [E]
            case 35840:    if (xk0 < 0) xk0 = i; break; // xk_W1 [280,128] (first)
            default: break;
        }
    }
    const int xv0 = xk0 + 6, xq0 = xk0 + 12, o0 = xk0 + 18;

    const float* h   = (const float*)d_in[ih];
    const float* rf  = (const float*)d_in[ir];
    const float* ef  = (const float*)d_in[ief];
    const float* ew  = (const float*)d_in[iew];
    const int*   ei  = (const int*)d_in[iei];
    const int N = in_sizes[ih] / 128;
    const int E = in_sizes[iew];
    const int* srcI = ei;
    const int* dstI = ei + E;

#define G(base, off) ((const float*)d_in[(base) + (off)])
    float* outp = (float*)d_out;

    // 1. init scratch
    init_kernel<<<(N * 128 + 255) / 256, 256>>>(N);
    // 2. node prep: q MLP + 4 projections
    nodeprep_kernel<<<(N + TILE - 1) / TILE, NTHREADS>>>(
        h, N, G(xq0,0), G(xq0,1), G(xq0,2), G(xq0,3), G(xq0,4), G(xq0,5),
        G(xk0,0), G(xv0,0));
    // 3. edge pass A: k MLP + scores + max
    edgeA_kernel<<<(E + TILE - 1) / TILE, NTHREADS>>>(
        rf, ef, srcI, dstI, E,
        G(xk0,0), G(xk0,1), G(xk0,2), G(xk0,3), G(xk0,4), G(xk0,5));
    // 4. exp + denominator
    softmax_kernel<<<(E * 16 + 255) / 256, 256>>>(dstI, E);
    // 5. edge pass B: v MLP + fused alpha*v scatter
    edgeB_kernel<<<(E + TILE - 1) / TILE, NTHREADS>>>(
        rf, ef, ew, srcI, dstI, E,
        G(xv0,0), G(xv0,1), G(xv0,2), G(xv0,3), G(xv0,4), G(xv0,5));
    // 6. output MLP on concat(attn, h)
    out_kernel<<<(N + TILE - 1) / TILE, NTHREADS>>>(
        h, outp, N, G(o0,0), G(o0,1), G(o0,2), G(o0,3), G(o0,4), G(o0,5));
#undef G
}

// round 7
// speedup vs baseline: 1.0229x; 1.0229x over previous
#include <cuda_runtime.h>
#include <math.h>

#define TILE 16
#define NTHREADS 128
#define NMAX 50000
#define EMAX 600000
#define LDH 132   // padded smem row stride (132 mod 32 == 4 -> conflict-free frags)
#define LDO 260   // padded stride for 256-wide input tiles

// weight split offsets (elements)
#define OFF_QW1 0
#define OFF_QW2 16384
#define OFF_KW1 32768
#define OFF_KW2 68608
#define OFF_VW1 84992
#define OFF_VW2 120832
#define OFF_OW1 137216
#define OFF_OW2 169984
#define W_TOTAL 186368

// ---------------- device scratch (no allocations allowed) ----------------
__device__ float g_q[NMAX * 128];      // q = MLP_q(h)
__device__ float g_kHd[NMAX * 128];    // h @ kW1[24:152]
__device__ float g_kHs[NMAX * 128];    // h @ kW1[152:280]
__device__ float g_vHd[NMAX * 128];    // h @ vW1[24:152]
__device__ float g_vHs[NMAX * 128];    // h @ vW1[152:280]
__device__ float g_attn[NMAX * 128];   // segment-summed alpha*v
__device__ float g_mx[NMAX * 16];      // per-(node,head) running max
__device__ float g_den[NMAX * 16];     // per-(node,head) exp-sum
__device__ float g_scores[EMAX * 16];  // scores, then exp(scores-max) in place
__device__ unsigned g_whi[W_TOTAL];    // tf32 hi split of all weight matrices
__device__ unsigned g_wlo[W_TOTAL];    // tf32 lo split

// ---------------- tf32 helpers ----------------
__device__ __forceinline__ unsigned cvt_tf32(float x) {
    unsigned r;
    asm("cvt.rna.tf32.f32 %0, %1;" : "=r"(r) : "f"(x));
    return r;
}

__device__ __forceinline__ void mma8(float (&c)[4], unsigned a0, unsigned a1,
                                     unsigned a2, unsigned a3,
                                     unsigned b0, unsigned b1) {
    asm("mma.sync.aligned.m16n8k8.row.col.f32.tf32.tf32.f32 "
        "{%0,%1,%2,%3}, {%4,%5,%6,%7}, {%8,%9}, {%0,%1,%2,%3};"
        : "+f"(c[0]), "+f"(c[1]), "+f"(c[2]), "+f"(c[3])
        : "r"(a0), "r"(a1), "r"(a2), "r"(a3), "r"(b0), "r"(b1));
}

// [16, KIN] (smem, stride LDA) @ [KIN, 128] (pre-split tf32 global) -> C
// 3xTF32: fp32-accurate. 4 warps, warp w owns output cols [32w, 32w+32).
// If GLOBAL: C[(row0+e)*128 + n]; else C is smem with stride LDH.
template <int KIN, int LDA, bool BIAS, bool GLOBAL>
__device__ __forceinline__ void mma_gemm16(
    const float* __restrict__ A_s,
    const unsigned* __restrict__ Bhi, const unsigned* __restrict__ Blo,
    const float* __restrict__ bias, float* __restrict__ C, int row0)
{
    const int lane = threadIdx.x & 31;
    const int warp = threadIdx.x >> 5;
    const int g = lane >> 2, tig = lane & 3;
    const int n0 = warp * 32;
    float c[4][4];
#pragma unroll
    for (int nt = 0; nt < 4; nt++) {
        float be = 0.f, bo = 0.f;
        if (BIAS) {
            be = bias[n0 + nt * 8 + 2 * tig];
            bo = bias[n0 + nt * 8 + 2 * tig + 1];
        }
        c[nt][0] = be; c[nt][1] = bo; c[nt][2] = be; c[nt][3] = bo;
    }
#pragma unroll 4
    for (int k = 0; k < KIN; k += 8) {
        const float a0f = A_s[g * LDA + k + tig];
        const float a1f = A_s[(g + 8) * LDA + k + tig];
        const float a2f = A_s[g * LDA + k + 4 + tig];
        const float a3f = A_s[(g + 8) * LDA + k + 4 + tig];
        const unsigned ah0 = cvt_tf32(a0f), ah1 = cvt_tf32(a1f);
        const unsigned ah2 = cvt_tf32(a2f), ah3 = cvt_tf32(a3f);
        const unsigned al0 = cvt_tf32(a0f - __uint_as_float(ah0));
        const unsigned al1 = cvt_tf32(a1f - __uint_as_float(ah1));
        const unsigned al2 = cvt_tf32(a2f - __uint_as_float(ah2));
        const unsigned al3 = cvt_tf32(a3f - __uint_as_float(ah3));
#pragma unroll
        for (int nt = 0; nt < 4; nt++) {
            const int nc = n0 + nt * 8 + g;
            const unsigned bh0 = Bhi[(k + tig) * 128 + nc];
            const unsigned bh1 = Bhi[(k + 4 + tig) * 128 + nc];
            const unsigned bl0 = Blo[(k + tig) * 128 + nc];
            const unsigned bl1 = Blo[(k + 4 + tig) * 128 + nc];
            mma8(c[nt], ah0, ah1, ah2, ah3, bh0, bh1);
            mma8(c[nt], al0, al1, al2, al3, bh0, bh1);
            mma8(c[nt], ah0, ah1, ah2, ah3, bl0, bl1);
        }
    }
#pragma unroll
    for (int nt = 0; nt < 4; nt++) {
        const int ce = n0 + nt * 8 + 2 * tig;
        if (GLOBAL) {
            C[(row0 + g) * 128 + ce]     = c[nt][0];
            C[(row0 + g) * 128 + ce + 1] = c[nt][1];
            C[(row0 + g + 8) * 128 + ce]     = c[nt][2];
            C[(row0 + g + 8) * 128 + ce + 1] = c[nt][3];
        } else {
            C[g * LDH + ce]     = c[nt][0];
            C[g * LDH + ce + 1] = c[nt][1];
            C[(g + 8) * LDH + ce]     = c[nt][2];
            C[(g + 8) * LDH + ce + 1] = c[nt][3];
        }
    }
}

// monotone float atomic max via signed/unsigned int tricks (init to -inf)
__device__ __forceinline__ void atomicMaxF(float* addr, float v) {
    if (v >= 0.f) atomicMax((int*)addr, __float_as_int(v));
    else          atomicMin((unsigned int*)addr, __float_as_uint(v));
}

// ---------------- LN(+affine)+ReLU over hid_s rows (stride LDH) ----------------
__device__ __forceinline__ void ln_relu(float* hid_s, float* mu_s, float* rs_s,
                                        const float* __restrict__ gam,
                                        const float* __restrict__ bet) {
    const int t = threadIdx.x;
    const int w = t >> 5, lane = t & 31;
    __syncthreads();
    for (int e = w; e < TILE; e += 4) {
        float s = 0.f, s2 = 0.f;
#pragma unroll
        for (int j = 0; j < 4; j++) {
            const float v = hid_s[e * LDH + lane + j * 32];
            s += v; s2 += v * v;
        }
#pragma unroll
        for (int o = 16; o; o >>= 1) {
            s  += __shfl_down_sync(0xffffffffu, s, o);
            s2 += __shfl_down_sync(0xffffffffu, s2, o);
        }
        if (lane == 0) {
            const float mu = s * (1.f / 128.f);
            const float var = s2 * (1.f / 128.f) - mu * mu;
            mu_s[e] = mu;
            rs_s[e] = rsqrtf(var + 1e-5f);
        }
    }
    __syncthreads();
    const float gt = gam[t], bt = bet[t];
#pragma unroll
    for (int e = 0; e < TILE; e++) {
        float v = hid_s[e * LDH + t];
        v = fmaf((v - mu_s[e]) * rs_s[e], gt, bt);
        hid_s[e * LDH + t] = fmaxf(v, 0.f);
    }
    __syncthreads();
}

// ---------------- kernels ----------------
__global__ void init_kernel(int n) {
    const int i = blockIdx.x * blockDim.x + threadIdx.x;
    if (i < n * 128) g_attn[i] = 0.f;
    if (i < n * 16) { g_mx[i] = __int_as_float(0xff800000); g_den[i] = 0.f; }
}

// split all weight matrices into tf32 hi/lo (runs every call; deterministic)
__global__ void split_kernel(const float* s0, const float* s1, const float* s2,
                             const float* s3, const float* s4, const float* s5,
                             const float* s6, const float* s7) {
    const int m = blockIdx.y;
    const float* src; int off, cnt;
    switch (m) {
        case 0: src = s0; off = OFF_QW1; cnt = 16384; break;
        case 1: src = s1; off = OFF_QW2; cnt = 16384; break;
        case 2: src = s2; off = OFF_KW1; cnt = 35840; break;
        case 3: src = s3; off = OFF_KW2; cnt = 16384; break;
        case 4: src = s4; off = OFF_VW1; cnt = 35840; break;
        case 5: src = s5; off = OFF_VW2; cnt = 16384; break;
        case 6: src = s6; off = OFF_OW1; cnt = 32768; break;
        default: src = s7; off = OFF_OW2; cnt = 16384; break;
    }
    for (int i = blockIdx.x * blockDim.x + threadIdx.x; i < cnt;
         i += gridDim.x * blockDim.x) {
        const float x = src[i];
        const unsigned hi = cvt_tf32(x);
        g_whi[off + i] = hi;
        g_wlo[off + i] = cvt_tf32(x - __uint_as_float(hi));
    }
}

// node prep: q MLP + 4 projections (kHd,kHs,vHd,vHs) — all via tensor mma
__global__ void __launch_bounds__(NTHREADS)
nodeprep_kernel(const float* __restrict__ h, int n,
                const float* qb1, const float* qg, const float* qbe,
                const float* qb2) {
    __shared__ float in_s[TILE * LDH];
    __shared__ float hid_s[TILE * LDH];
    __shared__ float mu_s[TILE], rs_s[TILE];
    const int t = threadIdx.x;
    const int n0 = blockIdx.x * TILE;
    for (int e = 0; e < TILE; e++) in_s[e * LDH + t] = h[(n0 + e) * 128 + t];
    __syncthreads();

    // q = MLP_q(h)
    mma_gemm16<128, LDH, true, false>(in_s, g_whi + OFF_QW1, g_wlo + OFF_QW1,
                                      qb1, hid_s, 0);
    ln_relu(hid_s, mu_s, rs_s, qg, qbe);
    mma_gemm16<128, LDH, true, true>(hid_s, g_whi + OFF_QW2, g_wlo + OFF_QW2,
                                     qb2, g_q, n0);
    // projections of h through W1 slices (no bias)
    mma_gemm16<128, LDH, false, true>(in_s, g_whi + OFF_KW1 + 24 * 128,
                                      g_wlo + OFF_KW1 + 24 * 128, (const float*)0,
                                      g_kHd, n0);
    mma_gemm16<128, LDH, false, true>(in_s, g_whi + OFF_KW1 + 152 * 128,
                                      g_wlo + OFF_KW1 + 152 * 128, (const float*)0,
                                      g_kHs, n0);
    mma_gemm16<128, LDH, false, true>(in_s, g_whi + OFF_VW1 + 24 * 128,
                                      g_wlo + OFF_VW1 + 24 * 128, (const float*)0,
                                      g_vHd, n0);
    mma_gemm16<128, LDH, false, true>(in_s, g_whi + OFF_VW1 + 152 * 128,
                                      g_wlo + OFF_VW1 + 152 * 128, (const float*)0,
                                      g_vHs, n0);
}

// edge pass A: k-MLP via gather-add + small GEMM (scalar) + tensor lin2, scores
__global__ void __launch_bounds__(NTHREADS)
edgeA_kernel(const float* __restrict__ rf, const float* __restrict__ ef,
             const int* __restrict__ srcI, const int* __restrict__ dstI, int Ecnt,
             const float* kW1, const float* kb1, const float* kg,
             const float* kbe, const float* kb2) {
    __shared__ __align__(16) float sm_in[TILE * 24];
    __shared__ float hid_s[TILE * LDH];
    __shared__ float out_s[TILE * LDH];
    __shared__ float mu_s[TILE], rs_s[TILE];
    __shared__ int dst_s[TILE], src_s[TILE];
    const int t = threadIdx.x;
    const int e0 = blockIdx.x * TILE;
    const int ne = min(TILE, Ecnt - e0);

    if (t < ne) { dst_s[t] = dstI[e0 + t]; src_s[t] = srcI[e0 + t]; }
    for (int j = t; j < ne * 24; j += NTHREADS) {
        const int e = j / 24, i = j % 24;
        sm_in[e * 24 + i] = (i < 4) ? ef[(e0 + e) * 4 + i] : rf[(e0 + e) * 20 + (i - 4)];
    }
    __syncthreads();

    // first layer: bias + gathered node projections + small GEMM over 24 dims
    float acc[TILE];
    const float bb1 = kb1[t];
#pragma unroll
    for (int e = 0; e < TILE; e++) {
        if (e < ne)
            acc[e] = bb1 + g_kHd[dst_s[e] * 128 + t] + g_kHs[src_s[e] * 128 + t];
        else acc[e] = 0.f;
    }
    for (int i = 0; i < 24; i += 4) {
        const float w0 = kW1[(i + 0) * 128 + t];
        const float w1 = kW1[(i + 1) * 128 + t];
        const float w2 = kW1[(i + 2) * 128 + t];
        const float w3 = kW1[(i + 3) * 128 + t];
#pragma unroll
        for (int e = 0; e < TILE; e++) {
            const float4 x = *(const float4*)(sm_in + e * 24 + i);
            acc[e] = fmaf(x.x, w0, acc[e]);
            acc[e] = fmaf(x.y, w1, acc[e]);
            acc[e] = fmaf(x.z, w2, acc[e]);
            acc[e] = fmaf(x.w, w3, acc[e]);
        }
    }
#pragma unroll
    for (int e = 0; e < TILE; e++) hid_s[e * LDH + t] = acc[e];
    ln_relu(hid_s, mu_s, rs_s, kg, kbe);

    mma_gemm16<128, LDH, true, false>(hid_s, g_whi + OFF_KW2, g_wlo + OFF_KW2,
                                      kb2, out_s, 0);
    __syncthreads();

    // per-head scores vs q[dst]
    for (int e = 0; e < ne; e++) {
        float val = out_s[e * LDH + t] * g_q[dst_s[e] * 128 + t];
        val += __shfl_down_sync(0xffffffffu, val, 4, 8);
        val += __shfl_down_sync(0xffffffffu, val, 2, 8);
        val += __shfl_down_sync(0xffffffffu, val, 1, 8);
        if ((t & 7) == 0) {
            const float sc = val * 0.35355339059327373f; // 1/sqrt(8)
            g_scores[(e0 + e) * 16 + (t >> 3)] = sc;
            atomicMaxF(&g_mx[dst_s[e] * 16 + (t >> 3)], sc);
        }
    }
}

__global__ void softmax_kernel(const int* __restrict__ dstI, int Ecnt) {
    const int gid = blockIdx.x * blockDim.x + threadIdx.x;
    if (gid >= Ecnt * 16) return;
    const int e = gid >> 4, hh = gid & 15;
    const int node = dstI[e];
    const float exv = expf(g_scores[gid] - g_mx[node * 16 + hh]);
    g_scores[gid] = exv;
    atomicAdd(&g_den[node * 16 + hh], exv);
}

// edge pass B: v-MLP via gather-add + tensor lin2 + fused alpha*v scatter
__global__ void __launch_bounds__(NTHREADS)
edgeB_kernel(const float* __restrict__ rf, const float* __restrict__ ef,
             const float* __restrict__ ew,
             const int* __restrict__ srcI, const int* __restrict__ dstI, int Ecnt,
             const float* vW1, const float* vb1, const float* vg,
             const float* vbe, const float* vb2) {
    __shared__ __align__(16) float sm_in[TILE * 24];
    __shared__ float hid_s[TILE * LDH];
    __shared__ float out_s[TILE * LDH];
    __shared__ float mu_s[TILE], rs_s[TILE], ew_s[TILE];
    __shared__ int dst_s[TILE], src_s[TILE];
    const int t = threadIdx.x;
    const int e0 = blockIdx.x * TILE;
    const int ne = min(TILE, Ecnt - e0);

    if (t < ne) {
        dst_s[t] = dstI[e0 + t];
        src_s[t] = srcI[e0 + t];
        ew_s[t] = ew[e0 + t];
    }
    for (int j = t; j < ne * 24; j += NTHREADS) {
        const int e = j / 24, i = j % 24;
        sm_in[e * 24 + i] = (i < 4) ? ef[(e0 + e) * 4 + i] : rf[(e0 + e) * 20 + (i - 4)];
    }
    __syncthreads();

    float acc[TILE];
    const float bb1 = vb1[t];
#pragma unroll
    for (int e = 0; e < TILE; e++) {
        if (e < ne)
            acc[e] = bb1 + g_vHd[dst_s[e] * 128 + t] + g_vHs[src_s[e] * 128 + t];
        else acc[e] = 0.f;
    }
    for (int i = 0; i < 24; i += 4) {
        const float w0 = vW1[(i + 0) * 128 + t];
        const float w1 = vW1[(i + 1) * 128 + t];
        const float w2 = vW1[(i + 2) * 128 + t];
        const float w3 = vW1[(i + 3) * 128 + t];
#pragma unroll
        for (int e = 0; e < TILE; e++) {
            const float4 x = *(const float4*)(sm_in + e * 24 + i);
            acc[e] = fmaf(x.x, w0, acc[e]);
            acc[e] = fmaf(x.y, w1, acc[e]);
            acc[e] = fmaf(x.z, w2, acc[e]);
            acc[e] = fmaf(x.w, w3, acc[e]);
        }
    }
#pragma unroll
    for (int e = 0; e < TILE; e++) hid_s[e * LDH + t] = acc[e];
    ln_relu(hid_s, mu_s, rs_s, vg, vbe);

    mma_gemm16<128, LDH, true, false>(hid_s, g_whi + OFF_VW2, g_wlo + OFF_VW2,
                                      vb2, out_s, 0);
    __syncthreads();

    // alpha * v * e_w, scattered to destination node
    const int hh = t >> 3;
    for (int e = 0; e < ne; e++) {
        const int dd = dst_s[e];
        const float alpha = g_scores[(e0 + e) * 16 + hh] / g_den[dd * 16 + hh];
        atomicAdd(&g_attn[dd * 128 + t], out_s[e * LDH + t] * ew_s[e] * alpha);
    }
}

__global__ void __launch_bounds__(NTHREADS)
out_kernel(const float* __restrict__ h, float* __restrict__ outp, int n,
           const float* b1, const float* gam, const float* bet,
           const float* b2) {
    __shared__ float in_s[TILE * LDO];
    __shared__ float hid_s[TILE * LDH];
    __shared__ float mu_s[TILE], rs_s[TILE];
    const int t = threadIdx.x;
    const int n0 = blockIdx.x * TILE;
    for (int e = 0; e < TILE; e++) {
        const int node = n0 + e;
        in_s[e * LDO + t] = g_attn[node * 128 + t];
        in_s[e * LDO + 128 + t] = h[node * 128 + t];
    }
    __syncthreads();
    mma_gemm16<256, LDO, true, false>(in_s, g_whi + OFF_OW1, g_wlo + OFF_OW1,
                                      b1, hid_s, 0);
    ln_relu(hid_s, mu_s, rs_s, gam, bet);
    mma_gemm16<128, LDH, true, true>(hid_s, g_whi + OFF_OW2, g_wlo + OFF_OW2,
                                     b2, outp, n0);
}

// ---------------- launch ----------------
extern "C" void kernel_launch(void* const* d_in, const int* in_sizes, int n_in,
                              void* d_out, int out_size) {
    int ih = -1, ir = -1, ief = -1, iei = -1, iew = -1, xk0 = -1;
    for (int i = 0; i < n_in; i++) {
        switch (in_sizes[i]) {
            case 6400000:  if (ih  < 0) ih  = i; break; // h [N,128]
            case 12000000: if (ir  < 0) ir  = i; break; // r_feat [E,20]
            case 2400000:  if (ief < 0) ief = i; break; // edge_feat [E,4]
            case 1200000:  if (iei < 0) iei = i; break; // edge_index [2,E]
            case 600000:   if (iew < 0) iew = i; break; // e_w [E]
            case 35840:    if (xk0 < 0) xk0 = i; break; // xk_W1 [280,128] (first)
            default: break;
        }
    }
    const int xv0 = xk0 + 6, xq0 = xk0 + 12, o0 = xk0 + 18;

    const float* h   = (const float*)d_in[ih];
    const float* rf  = (const float*)d_in[ir];
    const float* ef  = (const float*)d_in[ief];
    const float* ew  = (const float*)d_in[iew];
    const int*   ei  = (const int*)d_in[iei];
    const int N = in_sizes[ih] / 128;
    const int E = in_sizes[iew];
    const int* srcI = ei;
    const int* dstI = ei + E;

#define G(base, off) ((const float*)d_in[(base) + (off)])
    float* outp = (float*)d_out;

    // 1. init scratch
    init_kernel<<<(N * 128 + 255) / 256, 256>>>(N);
    // 2. tf32 hi/lo split of all weight matrices
    {
        dim3 grid(64, 8);
        split_kernel<<<grid, 256>>>(G(xq0,0), G(xq0,4), G(xk0,0), G(xk0,4),
                                    G(xv0,0), G(xv0,4), G(o0,0),  G(o0,4));
    }
    // 3. node prep: q MLP + 4 projections
    nodeprep_kernel<<<(N + TILE - 1) / TILE, NTHREADS>>>(
        h, N, G(xq0,1), G(xq0,2), G(xq0,3), G(xq0,5));
    // 4. edge pass A: k MLP + scores + max
    edgeA_kernel<<<(E + TILE - 1) / TILE, NTHREADS>>>(
        rf, ef, srcI, dstI, E,
        G(xk0,0), G(xk0,1), G(xk0,2), G(xk0,3), G(xk0,5));
    // 5. exp + denominator
    softmax_kernel<<<(E * 16 + 255) / 256, 256>>>(dstI, E);
    // 6. edge pass B: v MLP + fused alpha*v scatter
    edgeB_kernel<<<(E + TILE - 1) / TILE, NTHREADS>>>(
        rf, ef, ew, srcI, dstI, E,
        G(xv0,0), G(xv0,1), G(xv0,2), G(xv0,3), G(xv0,5));
    // 7. output MLP on concat(attn, h)
    out_kernel<<<(N + TILE - 1) / TILE, NTHREADS>>>(
        h, outp, N, G(o0,1), G(o0,2), G(o0,3), G(o0,5));
#undef G
}

// round 11
// speedup vs baseline: 1.5365x; 1.5021x over previous
#include <cuda_runtime.h>
#include <math.h>

#define TILE 16
#define NTHREADS 128
#define NMAX 50000
#define EMAX 600000
#define LDH 132   // padded smem row stride (132 mod 32 == 4 -> conflict-free frags)
#define LDO 260   // padded stride for 256-wide input tiles

// packed tf32 fragment arrays, offsets in uint4 units (each K x 128 matrix = K*64 uint4)
#define P_QW1  0
#define P_QW2  8192
#define P_KW1D 16384
#define P_KW1S 24576
#define P_VW1D 32768
#define P_VW1S 40960
#define P_KW2  49152
#define P_VW2  57344
#define P_OW1  65536
#define P_OW2  81920
#define P_TOTAL 90112

// ---------------- device scratch (no allocations allowed) ----------------
__device__ float g_q[NMAX * 128];      // q = MLP_q(h)
__device__ float g_kHd[NMAX * 128];    // h @ kW1[24:152]
__device__ float g_kHs[NMAX * 128];    // h @ kW1[152:280]
__device__ float g_vHd[NMAX * 128];    // h @ vW1[24:152]
__device__ float g_vHs[NMAX * 128];    // h @ vW1[152:280]
__device__ float g_attn[NMAX * 128];   // segment-summed alpha*v
__device__ float g_mx[NMAX * 16];      // per-(node,head) running max
__device__ float g_den[NMAX * 16];     // per-(node,head) exp-sum
__device__ float g_scores[EMAX * 16];  // scores, then exp(scores-max) in place
__device__ uint4 g_wpk[P_TOTAL];       // packed tf32 fragments: {bh0,bh1,bl0,bl1}

// ---------------- tf32 helpers ----------------
__device__ __forceinline__ unsigned cvt_tf32(float x) {
    unsigned r;
    asm("cvt.rna.tf32.f32 %0, %1;" : "=r"(r) : "f"(x));
    return r;
}

__device__ __forceinline__ void mma8(float (&c)[4], unsigned a0, unsigned a1,
                                     unsigned a2, unsigned a3,
                                     unsigned b0, unsigned b1) {
    asm("mma.sync.aligned.m16n8k8.row.col.f32.tf32.tf32.f32 "
        "{%0,%1,%2,%3}, {%4,%5,%6,%7}, {%8,%9}, {%0,%1,%2,%3};"
        : "+f"(c[0]), "+f"(c[1]), "+f"(c[2]), "+f"(c[3])
        : "r"(a0), "r"(a1), "r"(a2), "r"(a3), "r"(b0), "r"(b1));
}

// [16, KIN] (smem, stride LDA) @ [KIN, 128] (packed tf32 fragments) -> C
// 3xTF32: fp32-accurate. 4 warps, warp w owns output cols [32w, 32w+32).
// Bpk layout: uint4 index ((k/8)*128 + nc)*4 + tig -> {bh(k+tig), bh(k+4+tig), bl(k+tig), bl(k+4+tig)} at col nc
template <int KIN, int LDA, bool BIAS, bool GLOBAL>
__device__ __forceinline__ void mma_gemm16(
    const float* __restrict__ A_s, const uint4* __restrict__ Bpk,
    const float* __restrict__ bias, float* __restrict__ C, int row0)
{
    const int lane = threadIdx.x & 31;
    const int warp = threadIdx.x >> 5;
    const int g = lane >> 2, tig = lane & 3;
    const int n0 = warp * 32;
    float c[4][4];
#pragma unroll
    for (int nt = 0; nt < 4; nt++) {
        float be = 0.f, bo = 0.f;
        if (BIAS) {
            be = bias[n0 + nt * 8 + 2 * tig];
            bo = bias[n0 + nt * 8 + 2 * tig + 1];
        }
        c[nt][0] = be; c[nt][1] = bo; c[nt][2] = be; c[nt][3] = bo;
    }
#pragma unroll 4
    for (int k = 0; k < KIN; k += 8) {
        const float a0f = A_s[g * LDA + k + tig];
        const float a1f = A_s[(g + 8) * LDA + k + tig];
        const float a2f = A_s[g * LDA + k + 4 + tig];
        const float a3f = A_s[(g + 8) * LDA + k + 4 + tig];
        const unsigned ah0 = cvt_tf32(a0f), ah1 = cvt_tf32(a1f);
        const unsigned ah2 = cvt_tf32(a2f), ah3 = cvt_tf32(a3f);
        const unsigned al0 = cvt_tf32(a0f - __uint_as_float(ah0));
        const unsigned al1 = cvt_tf32(a1f - __uint_as_float(ah1));
        const unsigned al2 = cvt_tf32(a2f - __uint_as_float(ah2));
        const unsigned al3 = cvt_tf32(a3f - __uint_as_float(ah3));
        const int kbase = (k >> 3) * 128;
#pragma unroll
        for (int nt = 0; nt < 4; nt++) {
            const int nc = n0 + nt * 8 + g;
            const uint4 b = Bpk[(kbase + nc) * 4 + tig];
            mma8(c[nt], ah0, ah1, ah2, ah3, b.x, b.y);  // hi*hi
            mma8(c[nt], al0, al1, al2, al3, b.x, b.y);  // lo*hi
            mma8(c[nt], ah0, ah1, ah2, ah3, b.z, b.w);  // hi*lo
        }
    }
#pragma unroll
    for (int nt = 0; nt < 4; nt++) {
        const int ce = n0 + nt * 8 + 2 * tig;
        if (GLOBAL) {
            C[(row0 + g) * 128 + ce]     = c[nt][0];
            C[(row0 + g) * 128 + ce + 1] = c[nt][1];
            C[(row0 + g + 8) * 128 + ce]     = c[nt][2];
            C[(row0 + g + 8) * 128 + ce + 1] = c[nt][3];
        } else {
            C[g * LDH + ce]     = c[nt][0];
            C[g * LDH + ce + 1] = c[nt][1];
            C[(g + 8) * LDH + ce]     = c[nt][2];
            C[(g + 8) * LDH + ce + 1] = c[nt][3];
        }
    }
}

// monotone float atomic max via signed/unsigned int tricks (init to -inf)
__device__ __forceinline__ void atomicMaxF(float* addr, float v) {
    if (v >= 0.f) atomicMax((int*)addr, __float_as_int(v));
    else          atomicMin((unsigned int*)addr, __float_as_uint(v));
}

// ---------------- LN(+affine)+ReLU over hid_s rows (stride LDH) ----------------
__device__ __forceinline__ void ln_relu(float* hid_s, float* mu_s, float* rs_s,
                                        const float* __restrict__ gam,
                                        const float* __restrict__ bet) {
    const int t = threadIdx.x;
    const int w = t >> 5, lane = t & 31;
    __syncthreads();
    for (int e = w; e < TILE; e += 4) {
        float s = 0.f, s2 = 0.f;
#pragma unroll
        for (int j = 0; j < 4; j++) {
            const float v = hid_s[e * LDH + lane + j * 32];
            s += v; s2 += v * v;
        }
#pragma unroll
        for (int o = 16; o; o >>= 1) {
            s  += __shfl_down_sync(0xffffffffu, s, o);
            s2 += __shfl_down_sync(0xffffffffu, s2, o);
        }
        if (lane == 0) {
            const float mu = s * (1.f / 128.f);
            const float var = s2 * (1.f / 128.f) - mu * mu;
            mu_s[e] = mu;
            rs_s[e] = rsqrtf(var + 1e-5f);
        }
    }
    __syncthreads();
    const float gt = gam[t], bt = bet[t];
#pragma unroll
    for (int e = 0; e < TILE; e++) {
        float v = hid_s[e * LDH + t];
        v = fmaf((v - mu_s[e]) * rs_s[e], gt, bt);
        hid_s[e * LDH + t] = fmaxf(v, 0.f);
    }
    __syncthreads();
}

// ---------------- kernels ----------------
__global__ void init_kernel(int n) {
    const int i = blockIdx.x * blockDim.x + threadIdx.x;
    if (i < n * 128) g_attn[i] = 0.f;
    if (i < n * 16) { g_mx[i] = __int_as_float(0xff800000); g_den[i] = 0.f; }
}

// split + pack all weight matrices into per-thread tf32 fragment uint4s
__global__ void split_kernel(const float* qW1, const float* qW2,
                             const float* kW1, const float* kW2,
                             const float* vW1, const float* vW2,
                             const float* oW1, const float* oW2) {
    const int m = blockIdx.y;
    const float* src; int dst, K;
    switch (m) {
        case 0: src = qW1;             dst = P_QW1;  K = 128; break;
        case 1: src = qW2;             dst = P_QW2;  K = 128; break;
        case 2: src = kW1 + 24 * 128;  dst = P_KW1D; K = 128; break;
        case 3: src = kW1 + 152 * 128; dst = P_KW1S; K = 128; break;
        case 4: src = vW1 + 24 * 128;  dst = P_VW1D; K = 128; break;
        case 5: src = vW1 + 152 * 128; dst = P_VW1S; K = 128; break;
        case 6: src = kW2;             dst = P_KW2;  K = 128; break;
        case 7: src = vW2;             dst = P_VW2;  K = 128; break;
        case 8: src = oW1;             dst = P_OW1;  K = 256; break;
        default: src = oW2;            dst = P_OW2;  K = 128; break;
    }
    const int cnt = (K >> 3) * 128 * 4;  // (k8, nc, tig) triples
    for (int i = blockIdx.x * blockDim.x + threadIdx.x; i < cnt;
         i += gridDim.x * blockDim.x) {
        const int tig = i & 3;
        const int nc  = (i >> 2) & 127;
        const int k8  = i >> 9;
        const float x0 = src[(k8 * 8 + tig) * 128 + nc];
        const float x1 = src[(k8 * 8 + 4 + tig) * 128 + nc];
        uint4 b;
        b.x = cvt_tf32(x0);
        b.y = cvt_tf32(x1);
        b.z = cvt_tf32(x0 - __uint_as_float(b.x));
        b.w = cvt_tf32(x1 - __uint_as_float(b.y));
        g_wpk[dst + i] = b;
    }
}

// node prep: q MLP + 4 projections (kHd,kHs,vHd,vHs) — all via tensor mma
__global__ void __launch_bounds__(NTHREADS)
nodeprep_kernel(const float* __restrict__ h, int n,
                const float* qb1, const float* qg, const float* qbe,
                const float* qb2) {
    __shared__ float in_s[TILE * LDH];
    __shared__ float hid_s[TILE * LDH];
    __shared__ float mu_s[TILE], rs_s[TILE];
    const int t = threadIdx.x;
    const int n0 = blockIdx.x * TILE;
    for (int e = 0; e < TILE; e++) in_s[e * LDH + t] = h[(n0 + e) * 128 + t];
    __syncthreads();

    // q = MLP_q(h)
    mma_gemm16<128, LDH, true, false>(in_s, g_wpk + P_QW1, qb1, hid_s, 0);
    ln_relu(hid_s, mu_s, rs_s, qg, qbe);
    mma_gemm16<128, LDH, true, true>(hid_s, g_wpk + P_QW2, qb2, g_q, n0);
    // projections of h through W1 slices (no bias)
    mma_gemm16<128, LDH, false, true>(in_s, g_wpk + P_KW1D, (const float*)0, g_kHd, n0);
    mma_gemm16<128, LDH, false, true>(in_s, g_wpk + P_KW1S, (const float*)0, g_kHs, n0);
    mma_gemm16<128, LDH, false, true>(in_s, g_wpk + P_VW1D, (const float*)0, g_vHd, n0);
    mma_gemm16<128, LDH, false, true>(in_s, g_wpk + P_VW1S, (const float*)0, g_vHs, n0);
}

// edge pass A: k-MLP via gather-add + small GEMM (scalar) + tensor lin2, scores
__global__ void __launch_bounds__(NTHREADS)
edgeA_kernel(const float* __restrict__ rf, const float* __restrict__ ef,
             const int* __restrict__ srcI, const int* __restrict__ dstI, int Ecnt,
             const float* kW1, const float* kb1, const float* kg,
             const float* kbe, const float* kb2) {
    __shared__ __align__(16) float sm_in[TILE * 24];
    __shared__ float hid_s[TILE * LDH];
    __shared__ float out_s[TILE * LDH];
    __shared__ float mu_s[TILE], rs_s[TILE];
    __shared__ int dst_s[TILE], src_s[TILE];
    const int t = threadIdx.x;
    const int e0 = blockIdx.x * TILE;
    const int ne = min(TILE, Ecnt - e0);

    if (t < ne) { dst_s[t] = dstI[e0 + t]; src_s[t] = srcI[e0 + t]; }
    for (int j = t; j < ne * 24; j += NTHREADS) {
        const int e = j / 24, i = j % 24;
        sm_in[e * 24 + i] = (i < 4) ? ef[(e0 + e) * 4 + i] : rf[(e0 + e) * 20 + (i - 4)];
    }
    __syncthreads();

    // first layer: bias + gathered node projections + small GEMM over 24 dims
    float acc[TILE];
    const float bb1 = kb1[t];
#pragma unroll
    for (int e = 0; e < TILE; e++) {
        if (e < ne)
            acc[e] = bb1 + g_kHd[dst_s[e] * 128 + t] + g_kHs[src_s[e] * 128 + t];
        else acc[e] = 0.f;
    }
    for (int i = 0; i < 24; i += 4) {
        const float w0 = kW1[(i + 0) * 128 + t];
        const float w1 = kW1[(i + 1) * 128 + t];
        const float w2 = kW1[(i + 2) * 128 + t];
        const float w3 = kW1[(i + 3) * 128 + t];
#pragma unroll
        for (int e = 0; e < TILE; e++) {
            const float4 x = *(const float4*)(sm_in + e * 24 + i);
            acc[e] = fmaf(x.x, w0, acc[e]);
            acc[e] = fmaf(x.y, w1, acc[e]);
            acc[e] = fmaf(x.z, w2, acc[e]);
            acc[e] = fmaf(x.w, w3, acc[e]);
        }
    }
#pragma unroll
    for (int e = 0; e < TILE; e++) hid_s[e * LDH + t] = acc[e];
    ln_relu(hid_s, mu_s, rs_s, kg, kbe);

    mma_gemm16<128, LDH, true, false>(hid_s, g_wpk + P_KW2, kb2, out_s, 0);
    __syncthreads();

    // per-head scores vs q[dst]
    for (int e = 0; e < ne; e++) {
        float val = out_s[e * LDH + t] * g_q[dst_s[e] * 128 + t];
        val += __shfl_down_sync(0xffffffffu, val, 4, 8);
        val += __shfl_down_sync(0xffffffffu, val, 2, 8);
        val += __shfl_down_sync(0xffffffffu, val, 1, 8);
        if ((t & 7) == 0) {
            const float sc = val * 0.35355339059327373f; // 1/sqrt(8)
            g_scores[(e0 + e) * 16 + (t >> 3)] = sc;
            atomicMaxF(&g_mx[dst_s[e] * 16 + (t >> 3)], sc);
        }
    }
}

__global__ void softmax_kernel(const int* __restrict__ dstI, int Ecnt) {
    const int gid = blockIdx.x * blockDim.x + threadIdx.x;
    if (gid >= Ecnt * 16) return;
    const int e = gid >> 4, hh = gid & 15;
    const int node = dstI[e];
    const float exv = expf(g_scores[gid] - g_mx[node * 16 + hh]);
    g_scores[gid] = exv;
    atomicAdd(&g_den[node * 16 + hh], exv);
}

// edge pass B: v-MLP via gather-add + tensor lin2 + fused alpha*v scatter
__global__ void __launch_bounds__(NTHREADS)
edgeB_kernel(const float* __restrict__ rf, const float* __restrict__ ef,
             const float* __restrict__ ew,
             const int* __restrict__ srcI, const int* __restrict__ dstI, int Ecnt,
             const float* vW1, const float* vb1, const float* vg,
             const float* vbe, const float* vb2) {
    __shared__ __align__(16) float sm_in[TILE * 24];
    __shared__ float hid_s[TILE * LDH];
    __shared__ float out_s[TILE * LDH];
    __shared__ float mu_s[TILE], rs_s[TILE], ew_s[TILE];
    __shared__ int dst_s[TILE], src_s[TILE];
    const int t = threadIdx.x;
    const int e0 = blockIdx.x * TILE;
    const int ne = min(TILE, Ecnt - e0);

    if (t < ne) {
        dst_s[t] = dstI[e0 + t];
        src_s[t] = srcI[e0 + t];
        ew_s[t] = ew[e0 + t];
    }
    for (int j = t; j < ne * 24; j += NTHREADS) {
        const int e = j / 24, i = j % 24;
        sm_in[e * 24 + i] = (i < 4) ? ef[(e0 + e) * 4 + i] : rf[(e0 + e) * 20 + (i - 4)];
    }
    __syncthreads();

    float acc[TILE];
    const float bb1 = vb1[t];
#pragma unroll
    for (int e = 0; e < TILE; e++) {
        if (e < ne)
            acc[e] = bb1 + g_vHd[dst_s[e] * 128 + t] + g_vHs[src_s[e] * 128 + t];
        else acc[e] = 0.f;
    }
    for (int i = 0; i < 24; i += 4) {
        const float w0 = vW1[(i + 0) * 128 + t];
        const float w1 = vW1[(i + 1) * 128 + t];
        const float w2 = vW1[(i + 2) * 128 + t];
        const float w3 = vW1[(i + 3) * 128 + t];
#pragma unroll
        for (int e = 0; e < TILE; e++) {
            const float4 x = *(const float4*)(sm_in + e * 24 + i);
            acc[e] = fmaf(x.x, w0, acc[e]);
            acc[e] = fmaf(x.y, w1, acc[e]);
            acc[e] = fmaf(x.z, w2, acc[e]);
            acc[e] = fmaf(x.w, w3, acc[e]);
        }
    }
#pragma unroll
    for (int e = 0; e < TILE; e++) hid_s[e * LDH + t] = acc[e];
    ln_relu(hid_s, mu_s, rs_s, vg, vbe);

    mma_gemm16<128, LDH, true, false>(hid_s, g_wpk + P_VW2, vb2, out_s, 0);
    __syncthreads();

    // alpha * v * e_w, scattered to destination node
    const int hh = t >> 3;
    for (int e = 0; e < ne; e++) {
        const int dd = dst_s[e];
        const float alpha = g_scores[(e0 + e) * 16 + hh] / g_den[dd * 16 + hh];
        atomicAdd(&g_attn[dd * 128 + t], out_s[e * LDH + t] * ew_s[e] * alpha);
    }
}

__global__ void __launch_bounds__(NTHREADS)
out_kernel(const float* __restrict__ h, float* __restrict__ outp, int n,
           const float* b1, const float* gam, const float* bet,
           const float* b2) {
    __shared__ float in_s[TILE * LDO];
    __shared__ float hid_s[TILE * LDH];
    __shared__ float mu_s[TILE], rs_s[TILE];
    const int t = threadIdx.x;
    const int n0 = blockIdx.x * TILE;
    for (int e = 0; e < TILE; e++) {
        const int node = n0 + e;
        in_s[e * LDO + t] = g_attn[node * 128 + t];
        in_s[e * LDO + 128 + t] = h[node * 128 + t];
    }
    __syncthreads();
    mma_gemm16<256, LDO, true, false>(in_s, g_wpk + P_OW1, b1, hid_s, 0);
    ln_relu(hid_s, mu_s, rs_s, gam, bet);
    mma_gemm16<128, LDH, true, true>(hid_s, g_wpk + P_OW2, b2, outp, n0);
}

// ---------------- launch ----------------
extern "C" void kernel_launch(void* const* d_in, const int* in_sizes, int n_in,
                              void* d_out, int out_size) {
    int ih = -1, ir = -1, ief = -1, iei = -1, iew = -1, xk0 = -1;
    for (int i = 0; i < n_in; i++) {
        switch (in_sizes[i]) {
            case 6400000:  if (ih  < 0) ih  = i; break; // h [N,128]
            case 12000000: if (ir  < 0) ir  = i; break; // r_feat [E,20]
            case 2400000:  if (ief < 0) ief = i; break; // edge_feat [E,4]
            case 1200000:  if (iei < 0) iei = i; break; // edge_index [2,E]
            case 600000:   if (iew < 0) iew = i; break; // e_w [E]
            case 35840:    if (xk0 < 0) xk0 = i; break; // xk_W1 [280,128] (first)
            default: break;
        }
    }
    const int xv0 = xk0 + 6, xq0 = xk0 + 12, o0 = xk0 + 18;

    const float* h   = (const float*)d_in[ih];
    const float* rf  = (const float*)d_in[ir];
    const float* ef  = (const float*)d_in[ief];
    const float* ew  = (const float*)d_in[iew];
    const int*   ei  = (const int*)d_in[iei];
    const int N = in_sizes[ih] / 128;
    const int E = in_sizes[iew];
    const int* srcI = ei;
    const int* dstI = ei + E;

#define G(base, off) ((const float*)d_in[(base) + (off)])
    float* outp = (float*)d_out;

    // 1. init scratch
    init_kernel<<<(N * 128 + 255) / 256, 256>>>(N);
    // 2. tf32 split + fragment pack of all weight matrices
    {
        dim3 grid(32, 10);
        split_kernel<<<grid, 256>>>(G(xq0,0), G(xq0,4), G(xk0,0), G(xk0,4),
                                    G(xv0,0), G(xv0,4), G(o0,0),  G(o0,4));
    }
    // 3. node prep: q MLP + 4 projections
    nodeprep_kernel<<<(N + TILE - 1) / TILE, NTHREADS>>>(
        h, N, G(xq0,1), G(xq0,2), G(xq0,3), G(xq0,5));
    // 4. edge pass A: k MLP + scores + max
    edgeA_kernel<<<(E + TILE - 1) / TILE, NTHREADS>>>(
        rf, ef, srcI, dstI, E,
        G(xk0,0), G(xk0,1), G(xk0,2), G(xk0,3), G(xk0,5));
    // 5. exp + denominator
    softmax_kernel<<<(E * 16 + 255) / 256, 256>>>(dstI, E);
    // 6. edge pass B: v MLP + fused alpha*v scatter
    edgeB_kernel<<<(E + TILE - 1) / TILE, NTHREADS>>>(
        rf, ef, ew, srcI, dstI, E,
        G(xv0,0), G(xv0,1), G(xv0,2), G(xv0,3), G(xv0,5));
    // 7. output MLP on concat(attn, h)
    out_kernel<<<(N + TILE - 1) / TILE, NTHREADS>>>(
        h, outp, N, G(o0,1), G(o0,2), G(o0,3), G(o0,5));
#undef G
}

// round 12
// speedup vs baseline: 1.9714x; 1.2831x over previous
#include <cuda_runtime.h>
#include <math.h>

#define TILE 16
#define NTHREADS 128
#define NMAX 50000
#define EMAX 600000
#define LDH 136   // padded smem row stride (136 mod 32 == 8 -> conflict-free float2 frags)
#define LDO 264   // padded stride for 256-wide input tiles

// packed bf16 fragment arrays, offsets in uint4 units (each 128x128 matrix = 4096 uint4)
#define P_QW1  0
#define P_QW2  4096
#define P_KW1D 8192
#define P_KW1S 12288
#define P_VW1D 16384
#define P_VW1S 20480
#define P_KW2  24576
#define P_VW2  28672
#define P_OW1  32768
#define P_OW2  40960
#define P_TOTAL 45056

// ---------------- device scratch (no allocations allowed) ----------------
__device__ float g_q[NMAX * 128];      // q = MLP_q(h)
__device__ float g_kHd[NMAX * 128];    // h @ kW1[24:152]
__device__ float g_kHs[NMAX * 128];    // h @ kW1[152:280]
__device__ float g_vHd[NMAX * 128];    // h @ vW1[24:152]
__device__ float g_vHs[NMAX * 128];    // h @ vW1[152:280]
__device__ float g_attn[NMAX * 128];   // segment-summed alpha*v
__device__ float g_mx[NMAX * 16];      // per-(node,head) running max
__device__ float g_den[NMAX * 16];     // per-(node,head) exp-sum
__device__ float g_scores[EMAX * 16];  // scores, then exp(scores-max) in place
__device__ uint4 g_wpk[P_TOTAL];       // packed bf16 fragments: {bh0,bh1,bl0,bl1}

// ---------------- bf16 helpers ----------------
// pack {lo, hi} floats into one bf16x2 word (lo -> lower half)
__device__ __forceinline__ unsigned pk_bf16x2(float lo, float hi) {
    unsigned r;
    asm("cvt.rn.bf16x2.f32 %0, %1, %2;" : "=r"(r) : "f"(hi), "f"(lo));
    return r;
}
// residual split: bf16x2 of (x - value(h)) per half (bf16 = top 16 bits of fp32)
__device__ __forceinline__ unsigned pk_residual(float2 x, unsigned h) {
    const float hlo = __uint_as_float(h << 16);
    const float hhi = __uint_as_float(h & 0xFFFF0000u);
    return pk_bf16x2(x.x - hlo, x.y - hhi);
}

__device__ __forceinline__ void mma16(float (&c)[4], unsigned a0, unsigned a1,
                                      unsigned a2, unsigned a3,
                                      unsigned b0, unsigned b1) {
    asm("mma.sync.aligned.m16n8k16.row.col.f32.bf16.bf16.f32 "
        "{%0,%1,%2,%3}, {%4,%5,%6,%7}, {%8,%9}, {%0,%1,%2,%3};"
        : "+f"(c[0]), "+f"(c[1]), "+f"(c[2]), "+f"(c[3])
        : "r"(a0), "r"(a1), "r"(a2), "r"(a3), "r"(b0), "r"(b1));
}

// [16, KIN] (smem fp32, stride LDA) @ [KIN, 128] (packed bf16 fragments) -> C
// 3xBF16: ah*bh + al*bh + ah*bl (error ~2^-16). 4 warps; warp w owns cols [32w,32w+32).
// Bpk layout: uint4 ((k/16)*128 + nc)*4 + tig -> {bh(rows 2tig,2tig+1), bh(rows +8), bl.., bl..} at col nc
template <int KIN, int LDA, bool BIAS, bool GLOBAL>
__device__ __forceinline__ void mma_gemm16(
    const float* __restrict__ A_s, const uint4* __restrict__ Bpk,
    const float* __restrict__ bias, float* __restrict__ C, int row0)
{
    const int lane = threadIdx.x & 31;
    const int warp = threadIdx.x >> 5;
    const int g = lane >> 2, tig = lane & 3;
    const int n0 = warp * 32;
    float c[4][4];
#pragma unroll
    for (int nt = 0; nt < 4; nt++) {
        float be = 0.f, bo = 0.f;
        if (BIAS) {
            be = bias[n0 + nt * 8 + 2 * tig];
            bo = bias[n0 + nt * 8 + 2 * tig + 1];
        }
        c[nt][0] = be; c[nt][1] = bo; c[nt][2] = be; c[nt][3] = bo;
    }
#pragma unroll
    for (int k = 0; k < KIN; k += 16) {
        const float2 p0 = *(const float2*)(A_s + g * LDA + k + 2 * tig);
        const float2 p1 = *(const float2*)(A_s + (g + 8) * LDA + k + 2 * tig);
        const float2 p2 = *(const float2*)(A_s + g * LDA + k + 8 + 2 * tig);
        const float2 p3 = *(const float2*)(A_s + (g + 8) * LDA + k + 8 + 2 * tig);
        const unsigned ah0 = pk_bf16x2(p0.x, p0.y);
        const unsigned ah1 = pk_bf16x2(p1.x, p1.y);
        const unsigned ah2 = pk_bf16x2(p2.x, p2.y);
        const unsigned ah3 = pk_bf16x2(p3.x, p3.y);
        const unsigned al0 = pk_residual(p0, ah0);
        const unsigned al1 = pk_residual(p1, ah1);
        const unsigned al2 = pk_residual(p2, ah2);
        const unsigned al3 = pk_residual(p3, ah3);
        const int kbase = (k >> 4) * 128;
#pragma unroll
        for (int nt = 0; nt < 4; nt++) {
            const int nc = n0 + nt * 8 + g;
            const uint4 b = Bpk[(kbase + nc) * 4 + tig];
            mma16(c[nt], ah0, ah1, ah2, ah3, b.x, b.y);  // hi*hi
            mma16(c[nt], al0, al1, al2, al3, b.x, b.y);  // lo*hi
            mma16(c[nt], ah0, ah1, ah2, ah3, b.z, b.w);  // hi*lo
        }
    }
#pragma unroll
    for (int nt = 0; nt < 4; nt++) {
        const int ce = n0 + nt * 8 + 2 * tig;
        if (GLOBAL) {
            C[(row0 + g) * 128 + ce]     = c[nt][0];
            C[(row0 + g) * 128 + ce + 1] = c[nt][1];
            C[(row0 + g + 8) * 128 + ce]     = c[nt][2];
            C[(row0 + g + 8) * 128 + ce + 1] = c[nt][3];
        } else {
            C[g * LDH + ce]     = c[nt][0];
            C[g * LDH + ce + 1] = c[nt][1];
            C[(g + 8) * LDH + ce]     = c[nt][2];
            C[(g + 8) * LDH + ce + 1] = c[nt][3];
        }
    }
}

// monotone float atomic max via signed/unsigned int tricks (init to -inf)
__device__ __forceinline__ void atomicMaxF(float* addr, float v) {
    if (v >= 0.f) atomicMax((int*)addr, __float_as_int(v));
    else          atomicMin((unsigned int*)addr, __float_as_uint(v));
}

// ---------------- LN(+affine)+ReLU over hid_s rows (stride LDH) ----------------
__device__ __forceinline__ void ln_relu(float* hid_s, float* mu_s, float* rs_s,
                                        const float* __restrict__ gam,
                                        const float* __restrict__ bet) {
    const int t = threadIdx.x;
    const int w = t >> 5, lane = t & 31;
    __syncthreads();
    for (int e = w; e < TILE; e += 4) {
        float s = 0.f, s2 = 0.f;
#pragma unroll
        for (int j = 0; j < 4; j++) {
            const float v = hid_s[e * LDH + lane + j * 32];
            s += v; s2 += v * v;
        }
#pragma unroll
        for (int o = 16; o; o >>= 1) {
            s  += __shfl_down_sync(0xffffffffu, s, o);
            s2 += __shfl_down_sync(0xffffffffu, s2, o);
        }
        if (lane == 0) {
            const float mu = s * (1.f / 128.f);
            const float var = s2 * (1.f / 128.f) - mu * mu;
            mu_s[e] = mu;
            rs_s[e] = rsqrtf(var + 1e-5f);
        }
    }
    __syncthreads();
    const float gt = gam[t], bt = bet[t];
#pragma unroll
    for (int e = 0; e < TILE; e++) {
        float v = hid_s[e * LDH + t];
        v = fmaf((v - mu_s[e]) * rs_s[e], gt, bt);
        hid_s[e * LDH + t] = fmaxf(v, 0.f);
    }
    __syncthreads();
}

// ---------------- kernels ----------------
__global__ void init_kernel(int n) {
    const int i = blockIdx.x * blockDim.x + threadIdx.x;
    if (i < n * 128) g_attn[i] = 0.f;
    if (i < n * 16) { g_mx[i] = __int_as_float(0xff800000); g_den[i] = 0.f; }
}

// split + pack all weight matrices into per-thread bf16 fragment uint4s
__global__ void split_kernel(const float* qW1, const float* qW2,
                             const float* kW1, const float* kW2,
                             const float* vW1, const float* vW2,
                             const float* oW1, const float* oW2) {
    const int m = blockIdx.y;
    const float* src; int dst, K;
    switch (m) {
        case 0: src = qW1;             dst = P_QW1;  K = 128; break;
        case 1: src = qW2;             dst = P_QW2;  K = 128; break;
        case 2: src = kW1 + 24 * 128;  dst = P_KW1D; K = 128; break;
        case 3: src = kW1 + 152 * 128; dst = P_KW1S; K = 128; break;
        case 4: src = vW1 + 24 * 128;  dst = P_VW1D; K = 128; break;
        case 5: src = vW1 + 152 * 128; dst = P_VW1S; K = 128; break;
        case 6: src = kW2;             dst = P_KW2;  K = 128; break;
        case 7: src = vW2;             dst = P_VW2;  K = 128; break;
        case 8: src = oW1;             dst = P_OW1;  K = 256; break;
        default: src = oW2;            dst = P_OW2;  K = 128; break;
    }
    const int cnt = (K >> 4) * 128 * 4;  // (k16, nc, tig) triples
    for (int i = blockIdx.x * blockDim.x + threadIdx.x; i < cnt;
         i += gridDim.x * blockDim.x) {
        const int tig = i & 3;
        const int nc  = (i >> 2) & 127;
        const int k16 = i >> 9;
        const int r0 = k16 * 16 + 2 * tig;
        float2 x0, x1;
        x0.x = src[(r0    ) * 128 + nc];
        x0.y = src[(r0 + 1) * 128 + nc];
        x1.x = src[(r0 + 8) * 128 + nc];
        x1.y = src[(r0 + 9) * 128 + nc];
        uint4 b;
        b.x = pk_bf16x2(x0.x, x0.y);
        b.y = pk_bf16x2(x1.x, x1.y);
        b.z = pk_residual(x0, b.x);
        b.w = pk_residual(x1, b.y);
        g_wpk[dst + i] = b;
    }
}

// node prep: q MLP + 4 projections (kHd,kHs,vHd,vHs) — all via tensor mma
__global__ void __launch_bounds__(NTHREADS)
nodeprep_kernel(const float* __restrict__ h, int n,
                const float* qb1, const float* qg, const float* qbe,
                const float* qb2) {
    __shared__ __align__(16) float in_s[TILE * LDH];
    __shared__ __align__(16) float hid_s[TILE * LDH];
    __shared__ float mu_s[TILE], rs_s[TILE];
    const int t = threadIdx.x;
    const int n0 = blockIdx.x * TILE;
    for (int e = 0; e < TILE; e++) in_s[e * LDH + t] = h[(n0 + e) * 128 + t];
    __syncthreads();

    // q = MLP_q(h)
    mma_gemm16<128, LDH, true, false>(in_s, g_wpk + P_QW1, qb1, hid_s, 0);
    ln_relu(hid_s, mu_s, rs_s, qg, qbe);
    mma_gemm16<128, LDH, true, true>(hid_s, g_wpk + P_QW2, qb2, g_q, n0);
    // projections of h through W1 slices (no bias)
    mma_gemm16<128, LDH, false, true>(in_s, g_wpk + P_KW1D, (const float*)0, g_kHd, n0);
    mma_gemm16<128, LDH, false, true>(in_s, g_wpk + P_KW1S, (const float*)0, g_kHs, n0);
    mma_gemm16<128, LDH, false, true>(in_s, g_wpk + P_VW1D, (const float*)0, g_vHd, n0);
    mma_gemm16<128, LDH, false, true>(in_s, g_wpk + P_VW1S, (const float*)0, g_vHs, n0);
}

// edge pass A: k-MLP via gather-add + small GEMM (scalar) + tensor lin2, scores
__global__ void __launch_bounds__(NTHREADS)
edgeA_kernel(const float* __restrict__ rf, const float* __restrict__ ef,
             const int* __restrict__ srcI, const int* __restrict__ dstI, int Ecnt,
             const float* kW1, const float* kb1, const float* kg,
             const float* kbe, const float* kb2) {
    __shared__ __align__(16) float sm_in[TILE * 24];
    __shared__ __align__(16) float hid_s[TILE * LDH];
    __shared__ __align__(16) float out_s[TILE * LDH];
    __shared__ float mu_s[TILE], rs_s[TILE];
    __shared__ int dst_s[TILE], src_s[TILE];
    const int t = threadIdx.x;
    const int e0 = blockIdx.x * TILE;
    const int ne = min(TILE, Ecnt - e0);

    if (t < ne) { dst_s[t] = dstI[e0 + t]; src_s[t] = srcI[e0 + t]; }
    for (int j = t; j < ne * 24; j += NTHREADS) {
        const int e = j / 24, i = j % 24;
        sm_in[e * 24 + i] = (i < 4) ? ef[(e0 + e) * 4 + i] : rf[(e0 + e) * 20 + (i - 4)];
    }
    __syncthreads();

    // first layer: bias + gathered node projections + small GEMM over 24 dims
    float acc[TILE];
    const float bb1 = kb1[t];
#pragma unroll
    for (int e = 0; e < TILE; e++) {
        if (e < ne)
            acc[e] = bb1 + g_kHd[dst_s[e] * 128 + t] + g_kHs[src_s[e] * 128 + t];
        else acc[e] = 0.f;
    }
    for (int i = 0; i < 24; i += 4) {
        const float w0 = kW1[(i + 0) * 128 + t];
        const float w1 = kW1[(i + 1) * 128 + t];
        const float w2 = kW1[(i + 2) * 128 + t];
        const float w3 = kW1[(i + 3) * 128 + t];
#pragma unroll
        for (int e = 0; e < TILE; e++) {
            const float4 x = *(const float4*)(sm_in + e * 24 + i);
            acc[e] = fmaf(x.x, w0, acc[e]);
            acc[e] = fmaf(x.y, w1, acc[e]);
            acc[e] = fmaf(x.z, w2, acc[e]);
            acc[e] = fmaf(x.w, w3, acc[e]);
        }
    }
#pragma unroll
    for (int e = 0; e < TILE; e++) hid_s[e * LDH + t] = acc[e];
    ln_relu(hid_s, mu_s, rs_s, kg, kbe);

    mma_gemm16<128, LDH, true, false>(hid_s, g_wpk + P_KW2, kb2, out_s, 0);
    __syncthreads();

    // per-head scores vs q[dst]
    for (int e = 0; e < ne; e++) {
        float val = out_s[e * LDH + t] * g_q[dst_s[e] * 128 + t];
        val += __shfl_down_sync(0xffffffffu, val, 4, 8);
        val += __shfl_down_sync(0xffffffffu, val, 2, 8);
        val += __shfl_down_sync(0xffffffffu, val, 1, 8);
        if ((t & 7) == 0) {
            const float sc = val * 0.35355339059327373f; // 1/sqrt(8)
            g_scores[(e0 + e) * 16 + (t >> 3)] = sc;
            atomicMaxF(&g_mx[dst_s[e] * 16 + (t >> 3)], sc);
        }
    }
}

__global__ void softmax_kernel(const int* __restrict__ dstI, int Ecnt) {
    const int gid = blockIdx.x * blockDim.x + threadIdx.x;
    if (gid >= Ecnt * 16) return;
    const int e = gid >> 4, hh = gid & 15;
    const int node = dstI[e];
    const float exv = expf(g_scores[gid] - g_mx[node * 16 + hh]);
    g_scores[gid] = exv;
    atomicAdd(&g_den[node * 16 + hh], exv);
}

// edge pass B: v-MLP via gather-add + tensor lin2 + fused alpha*v scatter
__global__ void __launch_bounds__(NTHREADS)
edgeB_kernel(const float* __restrict__ rf, const float* __restrict__ ef,
             const float* __restrict__ ew,
             const int* __restrict__ srcI, const int* __restrict__ dstI, int Ecnt,
             const float* vW1, const float* vb1, const float* vg,
             const float* vbe, const float* vb2) {
    __shared__ __align__(16) float sm_in[TILE * 24];
    __shared__ __align__(16) float hid_s[TILE * LDH];
    __shared__ __align__(16) float out_s[TILE * LDH];
    __shared__ float mu_s[TILE], rs_s[TILE], ew_s[TILE];
    __shared__ int dst_s[TILE], src_s[TILE];
    const int t = threadIdx.x;
    const int e0 = blockIdx.x * TILE;
    const int ne = min(TILE, Ecnt - e0);

    if (t < ne) {
        dst_s[t] = dstI[e0 + t];
        src_s[t] = srcI[e0 + t];
        ew_s[t] = ew[e0 + t];
    }
    for (int j = t; j < ne * 24; j += NTHREADS) {
        const int e = j / 24, i = j % 24;
        sm_in[e * 24 + i] = (i < 4) ? ef[(e0 + e) * 4 + i] : rf[(e0 + e) * 20 + (i - 4)];
    }
    __syncthreads();

    float acc[TILE];
    const float bb1 = vb1[t];
#pragma unroll
    for (int e = 0; e < TILE; e++) {
        if (e < ne)
            acc[e] = bb1 + g_vHd[dst_s[e] * 128 + t] + g_vHs[src_s[e] * 128 + t];
        else acc[e] = 0.f;
    }
    for (int i = 0; i < 24; i += 4) {
        const float w0 = vW1[(i + 0) * 128 + t];
        const float w1 = vW1[(i + 1) * 128 + t];
        const float w2 = vW1[(i + 2) * 128 + t];
        const float w3 = vW1[(i + 3) * 128 + t];
#pragma unroll
        for (int e = 0; e < TILE; e++) {
            const float4 x = *(const float4*)(sm_in + e * 24 + i);
            acc[e] = fmaf(x.x, w0, acc[e]);
            acc[e] = fmaf(x.y, w1, acc[e]);
            acc[e] = fmaf(x.z, w2, acc[e]);
            acc[e] = fmaf(x.w, w3, acc[e]);
        }
    }
#pragma unroll
    for (int e = 0; e < TILE; e++) hid_s[e * LDH + t] = acc[e];
    ln_relu(hid_s, mu_s, rs_s, vg, vbe);

    mma_gemm16<128, LDH, true, false>(hid_s, g_wpk + P_VW2, vb2, out_s, 0);
    __syncthreads();

    // alpha * v * e_w, scattered to destination node
    const int hh = t >> 3;
    for (int e = 0; e < ne; e++) {
        const int dd = dst_s[e];
        const float alpha = g_scores[(e0 + e) * 16 + hh] / g_den[dd * 16 + hh];
        atomicAdd(&g_attn[dd * 128 + t], out_s[e * LDH + t] * ew_s[e] * alpha);
    }
}

__global__ void __launch_bounds__(NTHREADS)
out_kernel(const float* __restrict__ h, float* __restrict__ outp, int n,
           const float* b1, const float* gam, const float* bet,
           const float* b2) {
    __shared__ __align__(16) float in_s[TILE * LDO];
    __shared__ __align__(16) float hid_s[TILE * LDH];
    __shared__ float mu_s[TILE], rs_s[TILE];
    const int t = threadIdx.x;
    const int n0 = blockIdx.x * TILE;
    for (int e = 0; e < TILE; e++) {
        const int node = n0 + e;
        in_s[e * LDO + t] = g_attn[node * 128 + t];
        in_s[e * LDO + 128 + t] = h[node * 128 + t];
    }
    __syncthreads();
    mma_gemm16<256, LDO, true, false>(in_s, g_wpk + P_OW1, b1, hid_s, 0);
    ln_relu(hid_s, mu_s, rs_s, gam, bet);
    mma_gemm16<128, LDH, true, true>(hid_s, g_wpk + P_OW2, b2, outp, n0);
}

// ---------------- launch ----------------
extern "C" void kernel_launch(void* const* d_in, const int* in_sizes, int n_in,
                              void* d_out, int out_size) {
    int ih = -1, ir = -1, ief = -1, iei = -1, iew = -1, xk0 = -1;
    for (int i = 0; i < n_in; i++) {
        switch (in_sizes[i]) {
            case 6400000:  if (ih  < 0) ih  = i; break; // h [N,128]
            case 12000000: if (ir  < 0) ir  = i; break; // r_feat [E,20]
            case 2400000:  if (ief < 0) ief = i; break; // edge_feat [E,4]
            case 1200000:  if (iei < 0) iei = i; break; // edge_index [2,E]
            case 600000:   if (iew < 0) iew = i; break; // e_w [E]
            case 35840:    if (xk0 < 0) xk0 = i; break; // xk_W1 [280,128] (first)
            default: break;
        }
    }
    const int xv0 = xk0 + 6, xq0 = xk0 + 12, o0 = xk0 + 18;

    const float* h   = (const float*)d_in[ih];
    const float* rf  = (const float*)d_in[ir];
    const float* ef  = (const float*)d_in[ief];
    const float* ew  = (const float*)d_in[iew];
    const int*   ei  = (const int*)d_in[iei];
    const int N = in_sizes[ih] / 128;
    const int E = in_sizes[iew];
    const int* srcI = ei;
    const int* dstI = ei + E;

#define G(base, off) ((const float*)d_in[(base) + (off)])
    float* outp = (float*)d_out;

    // 1. init scratch
    init_kernel<<<(N * 128 + 255) / 256, 256>>>(N);
    // 2. bf16 split + fragment pack of all weight matrices
    {
        dim3 grid(32, 10);
        split_kernel<<<grid, 256>>>(G(xq0,0), G(xq0,4), G(xk0,0), G(xk0,4),
                                    G(xv0,0), G(xv0,4), G(o0,0),  G(o0,4));
    }
    // 3. node prep: q MLP + 4 projections
    nodeprep_kernel<<<(N + TILE - 1) / TILE, NTHREADS>>>(
        h, N, G(xq0,1), G(xq0,2), G(xq0,3), G(xq0,5));
    // 4. edge pass A: k MLP + scores + max
    edgeA_kernel<<<(E + TILE - 1) / TILE, NTHREADS>>>(
        rf, ef, srcI, dstI, E,
        G(xk0,0), G(xk0,1), G(xk0,2), G(xk0,3), G(xk0,5));
    // 5. exp + denominator
    softmax_kernel<<<(E * 16 + 255) / 256, 256>>>(dstI, E);
    // 6. edge pass B: v MLP + fused alpha*v scatter
    edgeB_kernel<<<(E + TILE - 1) / TILE, NTHREADS>>>(
        rf, ef, ew, srcI, dstI, E,
        G(xv0,0), G(xv0,1), G(xv0,2), G(xv0,3), G(xv0,5));
    // 7. output MLP on concat(attn, h)
    out_kernel<<<(N + TILE - 1) / TILE, NTHREADS>>>(
        h, outp, N, G(o0,1), G(o0,2), G(o0,3), G(o0,5));
#undef G
}

// round 13
// speedup vs baseline: 2.0679x; 1.0490x over previous
#include <cuda_runtime.h>
#include <math.h>

#define TILE 16
#define NTHREADS 128
#define NMAX 50000
#define EMAX 600000
#define LDH 136   // padded smem row stride (136 mod 32 == 8 -> conflict-free float2 frags)
#define LDO 264   // padded stride for 256-wide input tiles
#define LDE 40    // padded stride for 32-wide edge-feature tiles (40 mod 32 == 8)

// packed bf16 fragment arrays, offsets in uint4 units
#define P_QW1  0
#define P_QW2  4096
#define P_KW1D 8192
#define P_KW1S 12288
#define P_VW1D 16384
#define P_VW1S 20480
#define P_KW2  24576
#define P_VW2  28672
#define P_OW1  32768
#define P_OW2  40960
#define P_KW1A 45056   // kW1[0:24] zero-padded to K=32 (1024 uint4)
#define P_VW1A 46080   // vW1[0:24] zero-padded to K=32
#define P_TOTAL 47104

// ---------------- device scratch (no allocations allowed) ----------------
__device__ float g_q[NMAX * 128];      // q = MLP_q(h)
__device__ float g_kHd[NMAX * 128];    // h @ kW1[24:152]
__device__ float g_kHs[NMAX * 128];    // h @ kW1[152:280]
__device__ float g_vHd[NMAX * 128];    // h @ vW1[24:152]
__device__ float g_vHs[NMAX * 128];    // h @ vW1[152:280]
__device__ float g_attn[NMAX * 128];   // segment-summed alpha*v
__device__ float g_mx[NMAX * 16];      // per-(node,head) running max
__device__ float g_den[NMAX * 16];     // per-(node,head) exp-sum
__device__ float g_scores[EMAX * 16];  // scores, then exp(scores-max) in place
__device__ uint4 g_wpk[P_TOTAL];       // packed bf16 fragments: {bh0,bh1,bl0,bl1}

// ---------------- bf16 helpers ----------------
__device__ __forceinline__ unsigned pk_bf16x2(float lo, float hi) {
    unsigned r;
    asm("cvt.rn.bf16x2.f32 %0, %1, %2;" : "=r"(r) : "f"(hi), "f"(lo));
    return r;
}
__device__ __forceinline__ unsigned pk_residual(float2 x, unsigned h) {
    const float hlo = __uint_as_float(h << 16);
    const float hhi = __uint_as_float(h & 0xFFFF0000u);
    return pk_bf16x2(x.x - hlo, x.y - hhi);
}

__device__ __forceinline__ void mma16(float (&c)[4], unsigned a0, unsigned a1,
                                      unsigned a2, unsigned a3,
                                      unsigned b0, unsigned b1) {
    asm("mma.sync.aligned.m16n8k16.row.col.f32.bf16.bf16.f32 "
        "{%0,%1,%2,%3}, {%4,%5,%6,%7}, {%8,%9}, {%0,%1,%2,%3};"
        : "+f"(c[0]), "+f"(c[1]), "+f"(c[2]), "+f"(c[3])
        : "r"(a0), "r"(a1), "r"(a2), "r"(a3), "r"(b0), "r"(b1));
}

// [16, KIN] (smem fp32, stride LDA) @ [KIN, 128] (packed bf16 fragments) -> C
// 3xBF16: ah*bh + al*bh + ah*bl. 4 warps; warp w owns cols [32w,32w+32).
template <int KIN, int LDA, bool BIAS, bool GLOBAL>
__device__ __forceinline__ void mma_gemm16(
    const float* __restrict__ A_s, const uint4* __restrict__ Bpk,
    const float* __restrict__ bias, float* __restrict__ C, int row0)
{
    const int lane = threadIdx.x & 31;
    const int warp = threadIdx.x >> 5;
    const int g = lane >> 2, tig = lane & 3;
    const int n0 = warp * 32;
    float c[4][4];
#pragma unroll
    for (int nt = 0; nt < 4; nt++) {
        float be = 0.f, bo = 0.f;
        if (BIAS) {
            be = bias[n0 + nt * 8 + 2 * tig];
            bo = bias[n0 + nt * 8 + 2 * tig + 1];
        }
        c[nt][0] = be; c[nt][1] = bo; c[nt][2] = be; c[nt][3] = bo;
    }
#pragma unroll
    for (int k = 0; k < KIN; k += 16) {
        const float2 p0 = *(const float2*)(A_s + g * LDA + k + 2 * tig);
        const float2 p1 = *(const float2*)(A_s + (g + 8) * LDA + k + 2 * tig);
        const float2 p2 = *(const float2*)(A_s + g * LDA + k + 8 + 2 * tig);
        const float2 p3 = *(const float2*)(A_s + (g + 8) * LDA + k + 8 + 2 * tig);
        const unsigned ah0 = pk_bf16x2(p0.x, p0.y);
        const unsigned ah1 = pk_bf16x2(p1.x, p1.y);
        const unsigned ah2 = pk_bf16x2(p2.x, p2.y);
        const unsigned ah3 = pk_bf16x2(p3.x, p3.y);
        const unsigned al0 = pk_residual(p0, ah0);
        const unsigned al1 = pk_residual(p1, ah1);
        const unsigned al2 = pk_residual(p2, ah2);
        const unsigned al3 = pk_residual(p3, ah3);
        const int kbase = (k >> 4) * 128;
#pragma unroll
        for (int nt = 0; nt < 4; nt++) {
            const int nc = n0 + nt * 8 + g;
            const uint4 b = Bpk[(kbase + nc) * 4 + tig];
            mma16(c[nt], ah0, ah1, ah2, ah3, b.x, b.y);
            mma16(c[nt], al0, al1, al2, al3, b.x, b.y);
            mma16(c[nt], ah0, ah1, ah2, ah3, b.z, b.w);
        }
    }
#pragma unroll
    for (int nt = 0; nt < 4; nt++) {
        const int ce = n0 + nt * 8 + 2 * tig;
        if (GLOBAL) {
            C[(row0 + g) * 128 + ce]     = c[nt][0];
            C[(row0 + g) * 128 + ce + 1] = c[nt][1];
            C[(row0 + g + 8) * 128 + ce]     = c[nt][2];
            C[(row0 + g + 8) * 128 + ce + 1] = c[nt][3];
        } else {
            C[g * LDH + ce]     = c[nt][0];
            C[g * LDH + ce + 1] = c[nt][1];
            C[(g + 8) * LDH + ce]     = c[nt][2];
            C[(g + 8) * LDH + ce + 1] = c[nt][3];
        }
    }
}

// edge first layer: [16, 32-padded edge feats] @ W1a  +  bias + Hd[dst] + Hs[src]
// accumulators initialized from gathers in fragment layout (LDG.64 pairs); output hid_s
__device__ __forceinline__ void mma_edge_l1(
    const float* __restrict__ A_s, const uint4* __restrict__ Bpk,
    const float* __restrict__ b1,
    const float* __restrict__ Hd, const float* __restrict__ Hs,
    const int* __restrict__ dst_s, const int* __restrict__ src_s,
    float* __restrict__ hid_s)
{
    const int lane = threadIdx.x & 31;
    const int warp = threadIdx.x >> 5;
    const int g = lane >> 2, tig = lane & 3;
    const int n0 = warp * 32;
    const int rd0 = dst_s[g] * 128, rs0 = src_s[g] * 128;
    const int rd8 = dst_s[g + 8] * 128, rs8 = src_s[g + 8] * 128;
    float c[4][4];
#pragma unroll
    for (int nt = 0; nt < 4; nt++) {
        const int ce = n0 + nt * 8 + 2 * tig;
        const float2 bd = *(const float2*)(b1 + ce);
        const float2 d0 = *(const float2*)(Hd + rd0 + ce);
        const float2 s0 = *(const float2*)(Hs + rs0 + ce);
        const float2 d8 = *(const float2*)(Hd + rd8 + ce);
        const float2 s8 = *(const float2*)(Hs + rs8 + ce);
        c[nt][0] = bd.x + d0.x + s0.x;
        c[nt][1] = bd.y + d0.y + s0.y;
        c[nt][2] = bd.x + d8.x + s8.x;
        c[nt][3] = bd.y + d8.y + s8.y;
    }
#pragma unroll
    for (int k = 0; k < 32; k += 16) {
        const float2 p0 = *(const float2*)(A_s + g * LDE + k + 2 * tig);
        const float2 p1 = *(const float2*)(A_s + (g + 8) * LDE + k + 2 * tig);
        const float2 p2 = *(const float2*)(A_s + g * LDE + k + 8 + 2 * tig);
        const float2 p3 = *(const float2*)(A_s + (g + 8) * LDE + k + 8 + 2 * tig);
        const unsigned ah0 = pk_bf16x2(p0.x, p0.y);
        const unsigned ah1 = pk_bf16x2(p1.x, p1.y);
        const unsigned ah2 = pk_bf16x2(p2.x, p2.y);
        const unsigned ah3 = pk_bf16x2(p3.x, p3.y);
        const unsigned al0 = pk_residual(p0, ah0);
        const unsigned al1 = pk_residual(p1, ah1);
        const unsigned al2 = pk_residual(p2, ah2);
        const unsigned al3 = pk_residual(p3, ah3);
        const int kbase = (k >> 4) * 128;
#pragma unroll
        for (int nt = 0; nt < 4; nt++) {
            const int nc = n0 + nt * 8 + g;
            const uint4 b = Bpk[(kbase + nc) * 4 + tig];
            mma16(c[nt], ah0, ah1, ah2, ah3, b.x, b.y);
            mma16(c[nt], al0, al1, al2, al3, b.x, b.y);
            mma16(c[nt], ah0, ah1, ah2, ah3, b.z, b.w);
        }
    }
#pragma unroll
    for (int nt = 0; nt < 4; nt++) {
        const int ce = n0 + nt * 8 + 2 * tig;
        hid_s[g * LDH + ce]     = c[nt][0];
        hid_s[g * LDH + ce + 1] = c[nt][1];
        hid_s[(g + 8) * LDH + ce]     = c[nt][2];
        hid_s[(g + 8) * LDH + ce + 1] = c[nt][3];
    }
}

// monotone float atomic max via signed/unsigned int tricks (init to -inf)
__device__ __forceinline__ void atomicMaxF(float* addr, float v) {
    if (v >= 0.f) atomicMax((int*)addr, __float_as_int(v));
    else          atomicMin((unsigned int*)addr, __float_as_uint(v));
}

// ---------------- LN(+affine)+ReLU over hid_s rows (stride LDH) ----------------
__device__ __forceinline__ void ln_relu(float* hid_s, float* mu_s, float* rs_s,
                                        const float* __restrict__ gam,
                                        const float* __restrict__ bet) {
    const int t = threadIdx.x;
    const int w = t >> 5, lane = t & 31;
    __syncthreads();
    for (int e = w; e < TILE; e += 4) {
        float s = 0.f, s2 = 0.f;
#pragma unroll
        for (int j = 0; j < 4; j++) {
            const float v = hid_s[e * LDH + lane + j * 32];
            s += v; s2 += v * v;
        }
#pragma unroll
        for (int o = 16; o; o >>= 1) {
            s  += __shfl_down_sync(0xffffffffu, s, o);
            s2 += __shfl_down_sync(0xffffffffu, s2, o);
        }
        if (lane == 0) {
            const float mu = s * (1.f / 128.f);
            const float var = s2 * (1.f / 128.f) - mu * mu;
            mu_s[e] = mu;
            rs_s[e] = rsqrtf(var + 1e-5f);
        }
    }
    __syncthreads();
    const float gt = gam[t], bt = bet[t];
#pragma unroll
    for (int e = 0; e < TILE; e++) {
        float v = hid_s[e * LDH + t];
        v = fmaf((v - mu_s[e]) * rs_s[e], gt, bt);
        hid_s[e * LDH + t] = fmaxf(v, 0.f);
    }
    __syncthreads();
}

// ---------------- kernels ----------------
__global__ void init_kernel(int n) {
    const int i = blockIdx.x * blockDim.x + threadIdx.x;
    if (i < n * 128) g_attn[i] = 0.f;
    if (i < n * 16) { g_mx[i] = __int_as_float(0xff800000); g_den[i] = 0.f; }
}

// split + pack all weight matrices into per-thread bf16 fragment uint4s
__global__ void split_kernel(const float* qW1, const float* qW2,
                             const float* kW1, const float* kW2,
                             const float* vW1, const float* vW2,
                             const float* oW1, const float* oW2) {
    const int m = blockIdx.y;
    const float* src; int dst, K, Klim;
    switch (m) {
        case 0:  src = qW1;             dst = P_QW1;  K = 128; Klim = 128; break;
        case 1:  src = qW2;             dst = P_QW2;  K = 128; Klim = 128; break;
        case 2:  src = kW1 + 24 * 128;  dst = P_KW1D; K = 128; Klim = 128; break;
        case 3:  src = kW1 + 152 * 128; dst = P_KW1S; K = 128; Klim = 128; break;
        case 4:  src = vW1 + 24 * 128;  dst = P_VW1D; K = 128; Klim = 128; break;
        case 5:  src = vW1 + 152 * 128; dst = P_VW1S; K = 128; Klim = 128; break;
        case 6:  src = kW2;             dst = P_KW2;  K = 128; Klim = 128; break;
        case 7:  src = vW2;             dst = P_VW2;  K = 128; Klim = 128; break;
        case 8:  src = oW1;             dst = P_OW1;  K = 256; Klim = 256; break;
        case 9:  src = oW2;             dst = P_OW2;  K = 128; Klim = 128; break;
        case 10: src = kW1;             dst = P_KW1A; K = 32;  Klim = 24;  break;
        default: src = vW1;             dst = P_VW1A; K = 32;  Klim = 24;  break;
    }
    const int cnt = (K >> 4) * 128 * 4;
    for (int i = blockIdx.x * blockDim.x + threadIdx.x; i < cnt;
         i += gridDim.x * blockDim.x) {
        const int tig = i & 3;
        const int nc  = (i >> 2) & 127;
        const int k16 = i >> 9;
        const int r0 = k16 * 16 + 2 * tig;
        float2 x0, x1;
        x0.x = (r0     < Klim) ? src[(r0    ) * 128 + nc] : 0.f;
        x0.y = (r0 + 1 < Klim) ? src[(r0 + 1) * 128 + nc] : 0.f;
        x1.x = (r0 + 8 < Klim) ? src[(r0 + 8) * 128 + nc] : 0.f;
        x1.y = (r0 + 9 < Klim) ? src[(r0 + 9) * 128 + nc] : 0.f;
        uint4 b;
        b.x = pk_bf16x2(x0.x, x0.y);
        b.y = pk_bf16x2(x1.x, x1.y);
        b.z = pk_residual(x0, b.x);
        b.w = pk_residual(x1, b.y);
        g_wpk[dst + i] = b;
    }
}

// node prep: q MLP + 4 projections (kHd,kHs,vHd,vHs) — all via tensor mma
__global__ void __launch_bounds__(NTHREADS)
nodeprep_kernel(const float* __restrict__ h, int n,
                const float* qb1, const float* qg, const float* qbe,
                const float* qb2) {
    __shared__ __align__(16) float in_s[TILE * LDH];
    __shared__ __align__(16) float hid_s[TILE * LDH];
    __shared__ float mu_s[TILE], rs_s[TILE];
    const int t = threadIdx.x;
    const int n0 = blockIdx.x * TILE;
    for (int e = 0; e < TILE; e++) in_s[e * LDH + t] = h[(n0 + e) * 128 + t];
    __syncthreads();

    mma_gemm16<128, LDH, true, false>(in_s, g_wpk + P_QW1, qb1, hid_s, 0);
    ln_relu(hid_s, mu_s, rs_s, qg, qbe);
    mma_gemm16<128, LDH, true, true>(hid_s, g_wpk + P_QW2, qb2, g_q, n0);
    mma_gemm16<128, LDH, false, true>(in_s, g_wpk + P_KW1D, (const float*)0, g_kHd, n0);
    mma_gemm16<128, LDH, false, true>(in_s, g_wpk + P_KW1S, (const float*)0, g_kHs, n0);
    mma_gemm16<128, LDH, false, true>(in_s, g_wpk + P_VW1D, (const float*)0, g_vHd, n0);
    mma_gemm16<128, LDH, false, true>(in_s, g_wpk + P_VW1S, (const float*)0, g_vHs, n0);
}

// edge pass A: all-MMA k-MLP (fragment-gather first layer) + scores + atomicMax
__global__ void __launch_bounds__(NTHREADS)
edgeA_kernel(const float* __restrict__ rf, const float* __restrict__ ef,
             const int* __restrict__ srcI, const int* __restrict__ dstI, int Ecnt,
             const float* kb1, const float* kg, const float* kbe,
             const float* kb2) {
    __shared__ __align__(16) float sm_in[TILE * LDE];
    __shared__ __align__(16) float hid_s[TILE * LDH];
    __shared__ __align__(16) float out_s[TILE * LDH];
    __shared__ float mu_s[TILE], rs_s[TILE];
    __shared__ int dst_s[TILE], src_s[TILE];
    const int t = threadIdx.x;
    const int e0 = blockIdx.x * TILE;
    const int ne = min(TILE, Ecnt - e0);

    if (t < TILE) {
        int idx = e0 + t; if (idx >= Ecnt) idx = Ecnt - 1;
        dst_s[t] = dstI[idx]; src_s[t] = srcI[idx];
    }
    // zero the K-pad columns (24..31) for all rows
    for (int j = t; j < TILE * 8; j += NTHREADS)
        sm_in[(j >> 3) * LDE + 24 + (j & 7)] = 0.f;
    for (int j = t; j < ne * 24; j += NTHREADS) {
        const int e = j / 24, i = j % 24;
        sm_in[e * LDE + i] = (i < 4) ? ef[(e0 + e) * 4 + i] : rf[(e0 + e) * 20 + (i - 4)];
    }
    // garbage rows e >= ne only affect their own (discarded) outputs
    __syncthreads();

    mma_edge_l1(sm_in, g_wpk + P_KW1A, kb1, g_kHd, g_kHs, dst_s, src_s, hid_s);
    ln_relu(hid_s, mu_s, rs_s, kg, kbe);  // leading __syncthreads covers hid_s stores
    mma_gemm16<128, LDH, true, false>(hid_s, g_wpk + P_KW2, kb2, out_s, 0);
    __syncthreads();

    // per-head scores vs q[dst]
    for (int e = 0; e < ne; e++) {
        float val = out_s[e * LDH + t] * g_q[dst_s[e] * 128 + t];
        val += __shfl_down_sync(0xffffffffu, val, 4, 8);
        val += __shfl_down_sync(0xffffffffu, val, 2, 8);
        val += __shfl_down_sync(0xffffffffu, val, 1, 8);
        if ((t & 7) == 0) {
            const float sc = val * 0.35355339059327373f; // 1/sqrt(8)
            g_scores[(e0 + e) * 16 + (t >> 3)] = sc;
            atomicMaxF(&g_mx[dst_s[e] * 16 + (t >> 3)], sc);
        }
    }
}

__global__ void softmax_kernel(const int* __restrict__ dstI, int Ecnt) {
    const int gid = blockIdx.x * blockDim.x + threadIdx.x;
    if (gid >= Ecnt * 16) return;
    const int e = gid >> 4, hh = gid & 15;
    const int node = dstI[e];
    const float exv = expf(g_scores[gid] - g_mx[node * 16 + hh]);
    g_scores[gid] = exv;
    atomicAdd(&g_den[node * 16 + hh], exv);
}

// edge pass B: all-MMA v-MLP + fused alpha*v scatter
__global__ void __launch_bounds__(NTHREADS)
edgeB_kernel(const float* __restrict__ rf, const float* __restrict__ ef,
             const float* __restrict__ ew,
             const int* __restrict__ srcI, const int* __restrict__ dstI, int Ecnt,
             const float* vb1, const float* vg, const float* vbe,
             const float* vb2) {
    __shared__ __align__(16) float sm_in[TILE * LDE];
    __shared__ __align__(16) float hid_s[TILE * LDH];
    __shared__ __align__(16) float out_s[TILE * LDH];
    __shared__ float mu_s[TILE], rs_s[TILE], ew_s[TILE];
    __shared__ int dst_s[TILE], src_s[TILE];
    const int t = threadIdx.x;
    const int e0 = blockIdx.x * TILE;
    const int ne = min(TILE, Ecnt - e0);

    if (t < TILE) {
        int idx = e0 + t; if (idx >= Ecnt) idx = Ecnt - 1;
        dst_s[t] = dstI[idx]; src_s[t] = srcI[idx];
        ew_s[t] = ew[idx];
    }
    for (int j = t; j < TILE * 8; j += NTHREADS)
        sm_in[(j >> 3) * LDE + 24 + (j & 7)] = 0.f;
    for (int j = t; j < ne * 24; j += NTHREADS) {
        const int e = j / 24, i = j % 24;
        sm_in[e * LDE + i] = (i < 4) ? ef[(e0 + e) * 4 + i] : rf[(e0 + e) * 20 + (i - 4)];
    }
    __syncthreads();

    mma_edge_l1(sm_in, g_wpk + P_VW1A, vb1, g_vHd, g_vHs, dst_s, src_s, hid_s);
    ln_relu(hid_s, mu_s, rs_s, vg, vbe);
    mma_gemm16<128, LDH, true, false>(hid_s, g_wpk + P_VW2, vb2, out_s, 0);
    __syncthreads();

    // alpha * v * e_w, scattered to destination node
    const int hh = t >> 3;
    for (int e = 0; e < ne; e++) {
        const int dd = dst_s[e];
        const float alpha = g_scores[(e0 + e) * 16 + hh] / g_den[dd * 16 + hh];
        atomicAdd(&g_attn[dd * 128 + t], out_s[e * LDH + t] * ew_s[e] * alpha);
    }
}

__global__ void __launch_bounds__(NTHREADS)
out_kernel(const float* __restrict__ h, float* __restrict__ outp, int n,
           const float* b1, const float* gam, const float* bet,
           const float* b2) {
    __shared__ __align__(16) float in_s[TILE * LDO];
    __shared__ __align__(16) float hid_s[TILE * LDH];
    __shared__ float mu_s[TILE], rs_s[TILE];
    const int t = threadIdx.x;
    const int n0 = blockIdx.x * TILE;
    for (int e = 0; e < TILE; e++) {
        const int node = n0 + e;
        in_s[e * LDO + t] = g_attn[node * 128 + t];
        in_s[e * LDO + 128 + t] = h[node * 128 + t];
    }
    __syncthreads();
    mma_gemm16<256, LDO, true, false>(in_s, g_wpk + P_OW1, b1, hid_s, 0);
    ln_relu(hid_s, mu_s, rs_s, gam, bet);
    mma_gemm16<128, LDH, true, true>(hid_s, g_wpk + P_OW2, b2, outp, n0);
}

// ---------------- launch ----------------
extern "C" void kernel_launch(void* const* d_in, const int* in_sizes, int n_in,
                              void* d_out, int out_size) {
    int ih = -1, ir = -1, ief = -1, iei = -1, iew = -1, xk0 = -1;
    for (int i = 0; i < n_in; i++) {
        switch (in_sizes[i]) {
            case 6400000:  if (ih  < 0) ih  = i; break; // h [N,128]
            case 12000000: if (ir  < 0) ir  = i; break; // r_feat [E,20]
            case 2400000:  if (ief < 0) ief = i; break; // edge_feat [E,4]
            case 1200000:  if (iei < 0) iei = i; break; // edge_index [2,E]
            case 600000:   if (iew < 0) iew = i; break; // e_w [E]
            case 35840:    if (xk0 < 0) xk0 = i; break; // xk_W1 [280,128] (first)
            default: break;
        }
    }
    const int xv0 = xk0 + 6, xq0 = xk0 + 12, o0 = xk0 + 18;

    const float* h   = (const float*)d_in[ih];
    const float* rf  = (const float*)d_in[ir];
    const float* ef  = (const float*)d_in[ief];
    const float* ew  = (const float*)d_in[iew];
    const int*   ei  = (const int*)d_in[iei];
    const int N = in_sizes[ih] / 128;
    const int E = in_sizes[iew];
    const int* srcI = ei;
    const int* dstI = ei + E;

#define G(base, off) ((const float*)d_in[(base) + (off)])
    float* outp = (float*)d_out;

    // 1. init scratch
    init_kernel<<<(N * 128 + 255) / 256, 256>>>(N);
    // 2. bf16 split + fragment pack of all weight matrices (incl. padded edge W1)
    {
        dim3 grid(32, 12);
        split_kernel<<<grid, 256>>>(G(xq0,0), G(xq0,4), G(xk0,0), G(xk0,4),
                                    G(xv0,0), G(xv0,4), G(o0,0),  G(o0,4));
    }
    // 3. node prep: q MLP + 4 projections
    nodeprep_kernel<<<(N + TILE - 1) / TILE, NTHREADS>>>(
        h, N, G(xq0,1), G(xq0,2), G(xq0,3), G(xq0,5));
    // 4. edge pass A: k MLP + scores + max
    edgeA_kernel<<<(E + TILE - 1) / TILE, NTHREADS>>>(
        rf, ef, srcI, dstI, E,
        G(xk0,1), G(xk0,2), G(xk0,3), G(xk0,5));
    // 5. exp + denominator
    softmax_kernel<<<(E * 16 + 255) / 256, 256>>>(dstI, E);
    // 6. edge pass B: v MLP + fused alpha*v scatter
    edgeB_kernel<<<(E + TILE - 1) / TILE, NTHREADS>>>(
        rf, ef, ew, srcI, dstI, E,
        G(xv0,1), G(xv0,2), G(xv0,3), G(xv0,5));
    // 7. output MLP on concat(attn, h)
    out_kernel<<<(N + TILE - 1) / TILE, NTHREADS>>>(
        h, outp, N, G(o0,1), G(o0,2), G(o0,3), G(o0,5));
#undef G
}

// round 14
// speedup vs baseline: 2.3373x; 1.1303x over previous
#include <cuda_runtime.h>
#include <math.h>

#define TILE 16
#define NTHREADS 128
#define NMAX 50000
#define EMAX 600000
#define LDH 136   // padded smem row stride (136 mod 32 == 8 -> conflict-free float2 frags)
#define LDO 264   // padded stride for 256-wide input tiles
#define LDE 40    // padded stride for 32-wide edge-feature tiles

// packed bf16 fragment arrays, offsets in uint4 units
#define P_QW1  0
#define P_QW2  4096
#define P_KW1D 8192
#define P_KW1S 12288
#define P_VW1D 16384
#define P_VW1S 20480
#define P_KW2  24576
#define P_VW2  28672
#define P_OW1  32768
#define P_OW2  40960
#define P_KW1A 45056   // kW1[0:24] zero-padded to K=32
#define P_VW1A 46080   // vW1[0:24] zero-padded to K=32
#define P_TOTAL 47104

// ---------------- device scratch (no allocations allowed) ----------------
__device__ float g_q[NMAX * 128];
__device__ float g_kHd[NMAX * 128];
__device__ float g_kHs[NMAX * 128];
__device__ float g_vHd[NMAX * 128];
__device__ float g_vHs[NMAX * 128];
__device__ float g_attn[NMAX * 128];
__device__ float g_mx[NMAX * 16];
__device__ float g_den[NMAX * 16];
__device__ float g_scores[EMAX * 16];
__device__ uint4 g_wpk[P_TOTAL];

// ---------------- bf16 helpers ----------------
__device__ __forceinline__ unsigned pk_bf16x2(float lo, float hi) {
    unsigned r;
    asm("cvt.rn.bf16x2.f32 %0, %1, %2;" : "=r"(r) : "f"(hi), "f"(lo));
    return r;
}
__device__ __forceinline__ unsigned pk_residual(float2 x, unsigned h) {
    const float hlo = __uint_as_float(h << 16);
    const float hhi = __uint_as_float(h & 0xFFFF0000u);
    return pk_bf16x2(x.x - hlo, x.y - hhi);
}

__device__ __forceinline__ void mma16(float (&c)[4], unsigned a0, unsigned a1,
                                      unsigned a2, unsigned a3,
                                      unsigned b0, unsigned b1) {
    asm("mma.sync.aligned.m16n8k16.row.col.f32.bf16.bf16.f32 "
        "{%0,%1,%2,%3}, {%4,%5,%6,%7}, {%8,%9}, {%0,%1,%2,%3};"
        : "+f"(c[0]), "+f"(c[1]), "+f"(c[2]), "+f"(c[3])
        : "r"(a0), "r"(a1), "r"(a2), "r"(a3), "r"(b0), "r"(b1));
}

// vector reduction: g_attn[ptr..ptr+1] += {x, y}  (sm_90+)
__device__ __forceinline__ void red_add_v2(float* ptr, float x, float y) {
    asm volatile("red.global.add.v2.f32 [%0], {%1, %2};"
                 :: "l"(ptr), "f"(x), "f"(y) : "memory");
}

// monotone float atomic max via signed/unsigned int tricks (init to -inf)
__device__ __forceinline__ void atomicMaxF(float* addr, float v) {
    if (v >= 0.f) atomicMax((int*)addr, __float_as_int(v));
    else          atomicMin((unsigned int*)addr, __float_as_uint(v));
}

// ---------------- MMA core: accumulators stay in registers ----------------
// [16, KIN] (smem fp32, stride LDA) @ [KIN, 128] (packed bf16 fragments) -> c[4][4]
// 3xBF16: ah*bh + al*bh + ah*bl. 4 warps; warp w owns cols [32w,32w+32).
template <int KIN, int LDA, bool BIAS>
__device__ __forceinline__ void mma_core(
    const float* __restrict__ A_s, const uint4* __restrict__ Bpk,
    const float* __restrict__ bias, float (&c)[4][4])
{
    const int lane = threadIdx.x & 31;
    const int warp = threadIdx.x >> 5;
    const int g = lane >> 2, tig = lane & 3;
    const int n0 = warp * 32;
#pragma unroll
    for (int nt = 0; nt < 4; nt++) {
        float be = 0.f, bo = 0.f;
        if (BIAS) {
            be = bias[n0 + nt * 8 + 2 * tig];
            bo = bias[n0 + nt * 8 + 2 * tig + 1];
        }
        c[nt][0] = be; c[nt][1] = bo; c[nt][2] = be; c[nt][3] = bo;
    }
#pragma unroll
    for (int k = 0; k < KIN; k += 16) {
        const float2 p0 = *(const float2*)(A_s + g * LDA + k + 2 * tig);
        const float2 p1 = *(const float2*)(A_s + (g + 8) * LDA + k + 2 * tig);
        const float2 p2 = *(const float2*)(A_s + g * LDA + k + 8 + 2 * tig);
        const float2 p3 = *(const float2*)(A_s + (g + 8) * LDA + k + 8 + 2 * tig);
        const unsigned ah0 = pk_bf16x2(p0.x, p0.y);
        const unsigned ah1 = pk_bf16x2(p1.x, p1.y);
        const unsigned ah2 = pk_bf16x2(p2.x, p2.y);
        const unsigned ah3 = pk_bf16x2(p3.x, p3.y);
        const unsigned al0 = pk_residual(p0, ah0);
        const unsigned al1 = pk_residual(p1, ah1);
        const unsigned al2 = pk_residual(p2, ah2);
        const unsigned al3 = pk_residual(p3, ah3);
        const int kbase = (k >> 4) * 128;
#pragma unroll
        for (int nt = 0; nt < 4; nt++) {
            const int nc = n0 + nt * 8 + g;
            const uint4 b = Bpk[(kbase + nc) * 4 + tig];
            mma16(c[nt], ah0, ah1, ah2, ah3, b.x, b.y);
            mma16(c[nt], al0, al1, al2, al3, b.x, b.y);
            mma16(c[nt], ah0, ah1, ah2, ah3, b.z, b.w);
        }
    }
}

// store fragments to smem (stride LDH) or global (row stride 128)
template <bool GLOBAL>
__device__ __forceinline__ void frag_store(float (&c)[4][4], float* __restrict__ C,
                                           int row0) {
    const int lane = threadIdx.x & 31;
    const int warp = threadIdx.x >> 5;
    const int g = lane >> 2, tig = lane & 3;
    const int n0 = warp * 32;
#pragma unroll
    for (int nt = 0; nt < 4; nt++) {
        const int ce = n0 + nt * 8 + 2 * tig;
        if (GLOBAL) {
            C[(row0 + g) * 128 + ce]     = c[nt][0];
            C[(row0 + g) * 128 + ce + 1] = c[nt][1];
            C[(row0 + g + 8) * 128 + ce]     = c[nt][2];
            C[(row0 + g + 8) * 128 + ce + 1] = c[nt][3];
        } else {
            C[g * LDH + ce]     = c[nt][0];
            C[g * LDH + ce + 1] = c[nt][1];
            C[(g + 8) * LDH + ce]     = c[nt][2];
            C[(g + 8) * LDH + ce + 1] = c[nt][3];
        }
    }
}

template <int KIN, int LDA, bool BIAS, bool GLOBAL>
__device__ __forceinline__ void mma_gemm16(
    const float* __restrict__ A_s, const uint4* __restrict__ Bpk,
    const float* __restrict__ bias, float* __restrict__ C, int row0)
{
    float c[4][4];
    mma_core<KIN, LDA, BIAS>(A_s, Bpk, bias, c);
    frag_store<GLOBAL>(c, C, row0);
}

// edge first layer: [16, 32-padded edge feats] @ W1a + bias + Hd[dst] + Hs[src] -> hid_s
__device__ __forceinline__ void mma_edge_l1(
    const float* __restrict__ A_s, const uint4* __restrict__ Bpk,
    const float* __restrict__ b1,
    const float* __restrict__ Hd, const float* __restrict__ Hs,
    const int* __restrict__ dst_s, const int* __restrict__ src_s,
    float* __restrict__ hid_s)
{
    const int lane = threadIdx.x & 31;
    const int warp = threadIdx.x >> 5;
    const int g = lane >> 2, tig = lane & 3;
    const int n0 = warp * 32;
    const int rd0 = dst_s[g] * 128, rs0 = src_s[g] * 128;
    const int rd8 = dst_s[g + 8] * 128, rs8 = src_s[g + 8] * 128;
    float c[4][4];
#pragma unroll
    for (int nt = 0; nt < 4; nt++) {
        const int ce = n0 + nt * 8 + 2 * tig;
        const float2 bd = *(const float2*)(b1 + ce);
        const float2 d0 = *(const float2*)(Hd + rd0 + ce);
        const float2 s0 = *(const float2*)(Hs + rs0 + ce);
        const float2 d8 = *(const float2*)(Hd + rd8 + ce);
        const float2 s8 = *(const float2*)(Hs + rs8 + ce);
        c[nt][0] = bd.x + d0.x + s0.x;
        c[nt][1] = bd.y + d0.y + s0.y;
        c[nt][2] = bd.x + d8.x + s8.x;
        c[nt][3] = bd.y + d8.y + s8.y;
    }
#pragma unroll
    for (int k = 0; k < 32; k += 16) {
        const float2 p0 = *(const float2*)(A_s + g * LDE + k + 2 * tig);
        const float2 p1 = *(const float2*)(A_s + (g + 8) * LDE + k + 2 * tig);
        const float2 p2 = *(const float2*)(A_s + g * LDE + k + 8 + 2 * tig);
        const float2 p3 = *(const float2*)(A_s + (g + 8) * LDE + k + 8 + 2 * tig);
        const unsigned ah0 = pk_bf16x2(p0.x, p0.y);
        const unsigned ah1 = pk_bf16x2(p1.x, p1.y);
        const unsigned ah2 = pk_bf16x2(p2.x, p2.y);
        const unsigned ah3 = pk_bf16x2(p3.x, p3.y);
        const unsigned al0 = pk_residual(p0, ah0);
        const unsigned al1 = pk_residual(p1, ah1);
        const unsigned al2 = pk_residual(p2, ah2);
        const unsigned al3 = pk_residual(p3, ah3);
        const int kbase = (k >> 4) * 128;
#pragma unroll
        for (int nt = 0; nt < 4; nt++) {
            const int nc = n0 + nt * 8 + g;
            const uint4 b = Bpk[(kbase + nc) * 4 + tig];
            mma16(c[nt], ah0, ah1, ah2, ah3, b.x, b.y);
            mma16(c[nt], al0, al1, al2, al3, b.x, b.y);
            mma16(c[nt], ah0, ah1, ah2, ah3, b.z, b.w);
        }
    }
    frag_store<false>(c, hid_s, 0);
}

// ---------------- LN(+affine)+ReLU over hid_s rows (stride LDH) ----------------
__device__ __forceinline__ void ln_relu(float* hid_s, float* mu_s, float* rs_s,
                                        const float* __restrict__ gam,
                                        const float* __restrict__ bet) {
    const int t = threadIdx.x;
    const int w = t >> 5, lane = t & 31;
    __syncthreads();
    for (int e = w; e < TILE; e += 4) {
        float s = 0.f, s2 = 0.f;
#pragma unroll
        for (int j = 0; j < 4; j++) {
            const float v = hid_s[e * LDH + lane + j * 32];
            s += v; s2 += v * v;
        }
#pragma unroll
        for (int o = 16; o; o >>= 1) {
            s  += __shfl_down_sync(0xffffffffu, s, o);
            s2 += __shfl_down_sync(0xffffffffu, s2, o);
        }
        if (lane == 0) {
            const float mu = s * (1.f / 128.f);
            const float var = s2 * (1.f / 128.f) - mu * mu;
            mu_s[e] = mu;
            rs_s[e] = rsqrtf(var + 1e-5f);
        }
    }
    __syncthreads();
    const float gt = gam[t], bt = bet[t];
#pragma unroll
    for (int e = 0; e < TILE; e++) {
        float v = hid_s[e * LDH + t];
        v = fmaf((v - mu_s[e]) * rs_s[e], gt, bt);
        hid_s[e * LDH + t] = fmaxf(v, 0.f);
    }
    __syncthreads();
}

// ---------------- kernels ----------------
__global__ void init_kernel(int n) {
    const int i = blockIdx.x * blockDim.x + threadIdx.x;
    if (i < n * 128) g_attn[i] = 0.f;
    if (i < n * 16) { g_mx[i] = __int_as_float(0xff800000); g_den[i] = 0.f; }
}

__global__ void split_kernel(const float* qW1, const float* qW2,
                             const float* kW1, const float* kW2,
                             const float* vW1, const float* vW2,
                             const float* oW1, const float* oW2) {
    const int m = blockIdx.y;
    const float* src; int dst, K, Klim;
    switch (m) {
        case 0:  src = qW1;             dst = P_QW1;  K = 128; Klim = 128; break;
        case 1:  src = qW2;             dst = P_QW2;  K = 128; Klim = 128; break;
        case 2:  src = kW1 + 24 * 128;  dst = P_KW1D; K = 128; Klim = 128; break;
        case 3:  src = kW1 + 152 * 128; dst = P_KW1S; K = 128; Klim = 128; break;
        case 4:  src = vW1 + 24 * 128;  dst = P_VW1D; K = 128; Klim = 128; break;
        case 5:  src = vW1 + 152 * 128; dst = P_VW1S; K = 128; Klim = 128; break;
        case 6:  src = kW2;             dst = P_KW2;  K = 128; Klim = 128; break;
        case 7:  src = vW2;             dst = P_VW2;  K = 128; Klim = 128; break;
        case 8:  src = oW1;             dst = P_OW1;  K = 256; Klim = 256; break;
        case 9:  src = oW2;             dst = P_OW2;  K = 128; Klim = 128; break;
        case 10: src = kW1;             dst = P_KW1A; K = 32;  Klim = 24;  break;
        default: src = vW1;             dst = P_VW1A; K = 32;  Klim = 24;  break;
    }
    const int cnt = (K >> 4) * 128 * 4;
    for (int i = blockIdx.x * blockDim.x + threadIdx.x; i < cnt;
         i += gridDim.x * blockDim.x) {
        const int tig = i & 3;
        const int nc  = (i >> 2) & 127;
        const int k16 = i >> 9;
        const int r0 = k16 * 16 + 2 * tig;
        float2 x0, x1;
        x0.x = (r0     < Klim) ? src[(r0    ) * 128 + nc] : 0.f;
        x0.y = (r0 + 1 < Klim) ? src[(r0 + 1) * 128 + nc] : 0.f;
        x1.x = (r0 + 8 < Klim) ? src[(r0 + 8) * 128 + nc] : 0.f;
        x1.y = (r0 + 9 < Klim) ? src[(r0 + 9) * 128 + nc] : 0.f;
        uint4 b;
        b.x = pk_bf16x2(x0.x, x0.y);
        b.y = pk_bf16x2(x1.x, x1.y);
        b.z = pk_residual(x0, b.x);
        b.w = pk_residual(x1, b.y);
        g_wpk[dst + i] = b;
    }
}

__global__ void __launch_bounds__(NTHREADS)
nodeprep_kernel(const float* __restrict__ h, int n,
                const float* qb1, const float* qg, const float* qbe,
                const float* qb2) {
    __shared__ __align__(16) float in_s[TILE * LDH];
    __shared__ __align__(16) float hid_s[TILE * LDH];
    __shared__ float mu_s[TILE], rs_s[TILE];
    const int t = threadIdx.x;
    const int n0 = blockIdx.x * TILE;
    for (int e = 0; e < TILE; e++) in_s[e * LDH + t] = h[(n0 + e) * 128 + t];
    __syncthreads();

    mma_gemm16<128, LDH, true, false>(in_s, g_wpk + P_QW1, qb1, hid_s, 0);
    ln_relu(hid_s, mu_s, rs_s, qg, qbe);
    mma_gemm16<128, LDH, true, true>(hid_s, g_wpk + P_QW2, qb2, g_q, n0);
    mma_gemm16<128, LDH, false, true>(in_s, g_wpk + P_KW1D, (const float*)0, g_kHd, n0);
    mma_gemm16<128, LDH, false, true>(in_s, g_wpk + P_KW1S, (const float*)0, g_kHs, n0);
    mma_gemm16<128, LDH, false, true>(in_s, g_wpk + P_VW1D, (const float*)0, g_vHd, n0);
    mma_gemm16<128, LDH, false, true>(in_s, g_wpk + P_VW1S, (const float*)0, g_vHs, n0);
}

// edge pass A: all-MMA k-MLP; scores computed straight from fragments
__global__ void __launch_bounds__(NTHREADS)
edgeA_kernel(const float* __restrict__ rf, const float* __restrict__ ef,
             const int* __restrict__ srcI, const int* __restrict__ dstI, int Ecnt,
             const float* kb1, const float* kg, const float* kbe,
             const float* kb2) {
    __shared__ __align__(16) float sm_in[TILE * LDE];
    __shared__ __align__(16) float hid_s[TILE * LDH];
    __shared__ float mu_s[TILE], rs_s[TILE];
    __shared__ int dst_s[TILE], src_s[TILE];
    const int t = threadIdx.x;
    const int e0 = blockIdx.x * TILE;
    const int ne = min(TILE, Ecnt - e0);

    if (t < TILE) {
        int idx = e0 + t; if (idx >= Ecnt) idx = Ecnt - 1;
        dst_s[t] = dstI[idx]; src_s[t] = srcI[idx];
    }
    for (int j = t; j < TILE * 8; j += NTHREADS)
        sm_in[(j >> 3) * LDE + 24 + (j & 7)] = 0.f;
    for (int j = t; j < ne * 24; j += NTHREADS) {
        const int e = j / 24, i = j % 24;
        sm_in[e * LDE + i] = (i < 4) ? ef[(e0 + e) * 4 + i] : rf[(e0 + e) * 20 + (i - 4)];
    }
    __syncthreads();

    mma_edge_l1(sm_in, g_wpk + P_KW1A, kb1, g_kHd, g_kHs, dst_s, src_s, hid_s);
    ln_relu(hid_s, mu_s, rs_s, kg, kbe);
    float c[4][4];
    mma_core<128, LDH, true>(hid_s, g_wpk + P_KW2, kb2, c);

    // score epilogue straight from fragments
    const int lane = t & 31, warp = t >> 5;
    const int g = lane >> 2, tig = lane & 3;
    const int n0 = warp * 32;
#pragma unroll
    for (int nt = 0; nt < 4; nt++) {
        const int ce = n0 + nt * 8 + 2 * tig;
        const float2 qa = *(const float2*)(g_q + dst_s[g] * 128 + ce);
        const float2 qb = *(const float2*)(g_q + dst_s[g + 8] * 128 + ce);
        float p0 = c[nt][0] * qa.x + c[nt][1] * qa.y;
        float p8 = c[nt][2] * qb.x + c[nt][3] * qb.y;
        p0 += __shfl_xor_sync(0xffffffffu, p0, 1);
        p0 += __shfl_xor_sync(0xffffffffu, p0, 2);
        p8 += __shfl_xor_sync(0xffffffffu, p8, 1);
        p8 += __shfl_xor_sync(0xffffffffu, p8, 2);
        if (tig == 0) {
            const int hh = warp * 4 + nt;
            if (e0 + g < Ecnt) {
                const float sc = p0 * 0.35355339059327373f; // 1/sqrt(8)
                g_scores[(e0 + g) * 16 + hh] = sc;
                atomicMaxF(&g_mx[dst_s[g] * 16 + hh], sc);
            }
            if (e0 + g + 8 < Ecnt) {
                const float sc = p8 * 0.35355339059327373f;
                g_scores[(e0 + g + 8) * 16 + hh] = sc;
                atomicMaxF(&g_mx[dst_s[g + 8] * 16 + hh], sc);
            }
        }
    }
}

__global__ void softmax_kernel(const int* __restrict__ dstI, int Ecnt) {
    const int gid = blockIdx.x * blockDim.x + threadIdx.x;
    if (gid >= Ecnt * 16) return;
    const int e = gid >> 4, hh = gid & 15;
    const int node = dstI[e];
    const float exv = expf(g_scores[gid] - g_mx[node * 16 + hh]);
    g_scores[gid] = exv;
    atomicAdd(&g_den[node * 16 + hh], exv);
}

// edge pass B: all-MMA v-MLP; alpha*v scattered straight from fragments (red.v2)
__global__ void __launch_bounds__(NTHREADS)
edgeB_kernel(const float* __restrict__ rf, const float* __restrict__ ef,
             const float* __restrict__ ew,
             const int* __restrict__ srcI, const int* __restrict__ dstI, int Ecnt,
             const float* vb1, const float* vg, const float* vbe,
             const float* vb2) {
    __shared__ __align__(16) float sm_in[TILE * LDE];
    __shared__ __align__(16) float hid_s[TILE * LDH];
    __shared__ float mu_s[TILE], rs_s[TILE], ew_s[TILE];
    __shared__ float alpha_s[TILE * 16];
    __shared__ int dst_s[TILE], src_s[TILE];
    const int t = threadIdx.x;
    const int e0 = blockIdx.x * TILE;
    const int ne = min(TILE, Ecnt - e0);

    if (t < TILE) {
        int idx = e0 + t; if (idx >= Ecnt) idx = Ecnt - 1;
        dst_s[t] = dstI[idx]; src_s[t] = srcI[idx];
        ew_s[t] = ew[idx];
    }
    for (int j = t; j < TILE * 8; j += NTHREADS)
        sm_in[(j >> 3) * LDE + 24 + (j & 7)] = 0.f;
    for (int j = t; j < ne * 24; j += NTHREADS) {
        const int e = j / 24, i = j % 24;
        sm_in[e * LDE + i] = (i < 4) ? ef[(e0 + e) * 4 + i] : rf[(e0 + e) * 20 + (i - 4)];
    }
    __syncthreads();

    // alpha (incl. e_w factor); visible to epilogue via ln_relu's barriers
    for (int j = t; j < ne * 16; j += NTHREADS) {
        const int e = j >> 4, hh = j & 15;
        alpha_s[j] = g_scores[(e0 + e) * 16 + hh] / g_den[dst_s[e] * 16 + hh] * ew_s[e];
    }

    mma_edge_l1(sm_in, g_wpk + P_VW1A, vb1, g_vHd, g_vHs, dst_s, src_s, hid_s);
    ln_relu(hid_s, mu_s, rs_s, vg, vbe);
    float c[4][4];
    mma_core<128, LDH, true>(hid_s, g_wpk + P_VW2, vb2, c);

    // scatter epilogue straight from fragments
    const int lane = t & 31, warp = t >> 5;
    const int g = lane >> 2, tig = lane & 3;
    const int n0 = warp * 32;
#pragma unroll
    for (int nt = 0; nt < 4; nt++) {
        const int hh = warp * 4 + nt;
        const int ce = n0 + nt * 8 + 2 * tig;
        if (e0 + g < Ecnt) {
            const float a = alpha_s[g * 16 + hh];
            red_add_v2(&g_attn[dst_s[g] * 128 + ce], c[nt][0] * a, c[nt][1] * a);
        }
        if (e0 + g + 8 < Ecnt) {
            const float a = alpha_s[(g + 8) * 16 + hh];
            red_add_v2(&g_attn[dst_s[g + 8] * 128 + ce], c[nt][2] * a, c[nt][3] * a);
        }
    }
}

__global__ void __launch_bounds__(NTHREADS)
out_kernel(const float* __restrict__ h, float* __restrict__ outp, int n,
           const float* b1, const float* gam, const float* bet,
           const float* b2) {
    __shared__ __align__(16) float in_s[TILE * LDO];
    __shared__ __align__(16) float hid_s[TILE * LDH];
    __shared__ float mu_s[TILE], rs_s[TILE];
    const int t = threadIdx.x;
    const int n0 = blockIdx.x * TILE;
    for (int e = 0; e < TILE; e++) {
        const int node = n0 + e;
        in_s[e * LDO + t] = g_attn[node * 128 + t];
        in_s[e * LDO + 128 + t] = h[node * 128 + t];
    }
    __syncthreads();
    mma_gemm16<256, LDO, true, false>(in_s, g_wpk + P_OW1, b1, hid_s, 0);
    ln_relu(hid_s, mu_s, rs_s, gam, bet);
    mma_gemm16<128, LDH, true, true>(hid_s, g_wpk + P_OW2, b2, outp, n0);
}

// ---------------- launch ----------------
extern "C" void kernel_launch(void* const* d_in, const int* in_sizes, int n_in,
                              void* d_out, int out_size) {
    int ih = -1, ir = -1, ief = -1, iei = -1, iew = -1, xk0 = -1;
    for (int i = 0; i < n_in; i++) {
        switch (in_sizes[i]) {
            case 6400000:  if (ih  < 0) ih  = i; break; // h [N,128]
            case 12000000: if (ir  < 0) ir  = i; break; // r_feat [E,20]
            case 2400000:  if (ief < 0) ief = i; break; // edge_feat [E,4]
            case 1200000:  if (iei < 0) iei = i; break; // edge_index [2,E]
            case 600000:   if (iew < 0) iew = i; break; // e_w [E]
            case 35840:    if (xk0 < 0) xk0 = i; break; // xk_W1 [280,128] (first)
            default: break;
        }
    }
    const int xv0 = xk0 + 6, xq0 = xk0 + 12, o0 = xk0 + 18;

    const float* h   = (const float*)d_in[ih];
    const float* rf  = (const float*)d_in[ir];
    const float* ef  = (const float*)d_in[ief];
    const float* ew  = (const float*)d_in[iew];
    const int*   ei  = (const int*)d_in[iei];
    const int N = in_sizes[ih] / 128;
    const int E = in_sizes[iew];
    const int* srcI = ei;
    const int* dstI = ei + E;

#define G(base, off) ((const float*)d_in[(base) + (off)])
    float* outp = (float*)d_out;

    init_kernel<<<(N * 128 + 255) / 256, 256>>>(N);
    {
        dim3 grid(32, 12);
        split_kernel<<<grid, 256>>>(G(xq0,0), G(xq0,4), G(xk0,0), G(xk0,4),
                                    G(xv0,0), G(xv0,4), G(o0,0),  G(o0,4));
    }
    nodeprep_kernel<<<(N + TILE - 1) / TILE, NTHREADS>>>(
        h, N, G(xq0,1), G(xq0,2), G(xq0,3), G(xq0,5));
    edgeA_kernel<<<(E + TILE - 1) / TILE, NTHREADS>>>(
        rf, ef, srcI, dstI, E,
        G(xk0,1), G(xk0,2), G(xk0,3), G(xk0,5));
    softmax_kernel<<<(E * 16 + 255) / 256, 256>>>(dstI, E);
    edgeB_kernel<<<(E + TILE - 1) / TILE, NTHREADS>>>(
        rf, ef, ew, srcI, dstI, E,
        G(xv0,1), G(xv0,2), G(xv0,3), G(xv0,5));
    out_kernel<<<(N + TILE - 1) / TILE, NTHREADS>>>(
        h, outp, N, G(o0,1), G(o0,2), G(o0,3), G(o0,5));
#undef G
}

// round 15
// speedup vs baseline: 2.4206x; 1.0356x over previous
#include <cuda_runtime.h>
#include <math.h>

#define TILE 16    // node kernels
#define TE 32      // edge kernels (two 16-row MMA tiles)
#define NTHREADS 128
#define NMAX 50000
#define EMAX 600000
#define LDH 136   // padded smem row stride (136 mod 32 == 8 -> conflict-free float2 frags)
#define LDO 264   // padded stride for 256-wide input tiles
#define LDE 40    // padded stride for 32-wide edge-feature tiles

// packed bf16 fragment arrays, offsets in uint4 units
#define P_QW1  0
#define P_QW2  4096
#define P_KW1D 8192
#define P_KW1S 12288
#define P_VW1D 16384
#define P_VW1S 20480
#define P_KW2  24576
#define P_VW2  28672
#define P_OW1  32768
#define P_OW2  40960
#define P_KW1A 45056   // kW1[0:24] zero-padded to K=32
#define P_VW1A 46080   // vW1[0:24] zero-padded to K=32
#define P_TOTAL 47104

// ---------------- device scratch (no allocations allowed) ----------------
__device__ float g_q[NMAX * 128];
__device__ float g_kHd[NMAX * 128];
__device__ float g_kHs[NMAX * 128];
__device__ float g_vHd[NMAX * 128];
__device__ float g_vHs[NMAX * 128];
__device__ float g_attn[NMAX * 128];
__device__ float g_mx[NMAX * 16];
__device__ float g_den[NMAX * 16];
__device__ float g_scores[EMAX * 16];
__device__ uint4 g_wpk[P_TOTAL];

// ---------------- bf16 helpers ----------------
__device__ __forceinline__ unsigned pk_bf16x2(float lo, float hi) {
    unsigned r;
    asm("cvt.rn.bf16x2.f32 %0, %1, %2;" : "=r"(r) : "f"(hi), "f"(lo));
    return r;
}
__device__ __forceinline__ unsigned pk_residual(float2 x, unsigned h) {
    const float hlo = __uint_as_float(h << 16);
    const float hhi = __uint_as_float(h & 0xFFFF0000u);
    return pk_bf16x2(x.x - hlo, x.y - hhi);
}

__device__ __forceinline__ void mma16(float (&c)[4], unsigned a0, unsigned a1,
                                      unsigned a2, unsigned a3,
                                      unsigned b0, unsigned b1) {
    asm("mma.sync.aligned.m16n8k16.row.col.f32.bf16.bf16.f32 "
        "{%0,%1,%2,%3}, {%4,%5,%6,%7}, {%8,%9}, {%0,%1,%2,%3};"
        : "+f"(c[0]), "+f"(c[1]), "+f"(c[2]), "+f"(c[3])
        : "r"(a0), "r"(a1), "r"(a2), "r"(a3), "r"(b0), "r"(b1));
}

// vector reduction: g_attn[ptr..ptr+1] += {x, y}  (sm_90+)
__device__ __forceinline__ void red_add_v2(float* ptr, float x, float y) {
    asm volatile("red.global.add.v2.f32 [%0], {%1, %2};"
                 :: "l"(ptr), "f"(x), "f"(y) : "memory");
}

// monotone float atomic max via signed/unsigned int tricks (init to -inf)
__device__ __forceinline__ void atomicMaxF(float* addr, float v) {
    if (v >= 0.f) atomicMax((int*)addr, __float_as_int(v));
    else          atomicMin((unsigned int*)addr, __float_as_uint(v));
}

// ---------------- A-fragment pack from smem ----------------
struct AFrag { unsigned ah0, ah1, ah2, ah3, al0, al1, al2, al3; };

template <int LDA>
__device__ __forceinline__ AFrag load_afrag(const float* __restrict__ A_s, int k,
                                            int g, int tig) {
    const float2 p0 = *(const float2*)(A_s + g * LDA + k + 2 * tig);
    const float2 p1 = *(const float2*)(A_s + (g + 8) * LDA + k + 2 * tig);
    const float2 p2 = *(const float2*)(A_s + g * LDA + k + 8 + 2 * tig);
    const float2 p3 = *(const float2*)(A_s + (g + 8) * LDA + k + 8 + 2 * tig);
    AFrag f;
    f.ah0 = pk_bf16x2(p0.x, p0.y); f.al0 = pk_residual(p0, f.ah0);
    f.ah1 = pk_bf16x2(p1.x, p1.y); f.al1 = pk_residual(p1, f.ah1);
    f.ah2 = pk_bf16x2(p2.x, p2.y); f.al2 = pk_residual(p2, f.ah2);
    f.ah3 = pk_bf16x2(p3.x, p3.y); f.al3 = pk_residual(p3, f.ah3);
    return f;
}

__device__ __forceinline__ void mma3(float (&c)[4], const AFrag& f, const uint4& b) {
    mma16(c, f.ah0, f.ah1, f.ah2, f.ah3, b.x, b.y);
    mma16(c, f.al0, f.al1, f.al2, f.al3, b.x, b.y);
    mma16(c, f.ah0, f.ah1, f.ah2, f.ah3, b.z, b.w);
}

// ---------------- single-tile MMA core (node kernels) ----------------
template <int KIN, int LDA, bool BIAS>
__device__ __forceinline__ void mma_core(
    const float* __restrict__ A_s, const uint4* __restrict__ Bpk,
    const float* __restrict__ bias, float (&c)[4][4])
{
    const int lane = threadIdx.x & 31;
    const int warp = threadIdx.x >> 5;
    const int g = lane >> 2, tig = lane & 3;
    const int n0 = warp * 32;
#pragma unroll
    for (int nt = 0; nt < 4; nt++) {
        float be = 0.f, bo = 0.f;
        if (BIAS) {
            be = bias[n0 + nt * 8 + 2 * tig];
            bo = bias[n0 + nt * 8 + 2 * tig + 1];
        }
        c[nt][0] = be; c[nt][1] = bo; c[nt][2] = be; c[nt][3] = bo;
    }
#pragma unroll
    for (int k = 0; k < KIN; k += 16) {
        const AFrag f = load_afrag<LDA>(A_s, k, g, tig);
        const int kbase = (k >> 4) * 128;
#pragma unroll
        for (int nt = 0; nt < 4; nt++) {
            const int nc = n0 + nt * 8 + g;
            const uint4 b = Bpk[(kbase + nc) * 4 + tig];
            mma3(c[nt], f, b);
        }
    }
}

// ---------------- dual-tile MMA core (edge kernels): B loaded once ----------------
template <int KIN, int LDA, bool BIAS>
__device__ __forceinline__ void mma_core_dual(
    const float* __restrict__ A_s, const uint4* __restrict__ Bpk,
    const float* __restrict__ bias, float (&c0)[4][4], float (&c1)[4][4])
{
    const int lane = threadIdx.x & 31;
    const int warp = threadIdx.x >> 5;
    const int g = lane >> 2, tig = lane & 3;
    const int n0 = warp * 32;
#pragma unroll
    for (int nt = 0; nt < 4; nt++) {
        float be = 0.f, bo = 0.f;
        if (BIAS) {
            be = bias[n0 + nt * 8 + 2 * tig];
            bo = bias[n0 + nt * 8 + 2 * tig + 1];
        }
        c0[nt][0] = be; c0[nt][1] = bo; c0[nt][2] = be; c0[nt][3] = bo;
        c1[nt][0] = be; c1[nt][1] = bo; c1[nt][2] = be; c1[nt][3] = bo;
    }
#pragma unroll
    for (int k = 0; k < KIN; k += 16) {
        const AFrag f0 = load_afrag<LDA>(A_s, k, g, tig);
        const AFrag f1 = load_afrag<LDA>(A_s + 16 * LDA, k, g, tig);
        const int kbase = (k >> 4) * 128;
#pragma unroll
        for (int nt = 0; nt < 4; nt++) {
            const int nc = n0 + nt * 8 + g;
            const uint4 b = Bpk[(kbase + nc) * 4 + tig];
            mma3(c0[nt], f0, b);
            mma3(c1[nt], f1, b);
        }
    }
}

// store fragments to smem (stride LDH, row offset r0) or global (row stride 128)
template <bool GLOBAL>
__device__ __forceinline__ void frag_store(float (&c)[4][4], float* __restrict__ C,
                                           int row0) {
    const int lane = threadIdx.x & 31;
    const int warp = threadIdx.x >> 5;
    const int g = lane >> 2, tig = lane & 3;
    const int n0 = warp * 32;
#pragma unroll
    for (int nt = 0; nt < 4; nt++) {
        const int ce = n0 + nt * 8 + 2 * tig;
        if (GLOBAL) {
            C[(row0 + g) * 128 + ce]     = c[nt][0];
            C[(row0 + g) * 128 + ce + 1] = c[nt][1];
            C[(row0 + g + 8) * 128 + ce]     = c[nt][2];
            C[(row0 + g + 8) * 128 + ce + 1] = c[nt][3];
        } else {
            C[(row0 + g) * LDH + ce]     = c[nt][0];
            C[(row0 + g) * LDH + ce + 1] = c[nt][1];
            C[(row0 + g + 8) * LDH + ce]     = c[nt][2];
            C[(row0 + g + 8) * LDH + ce + 1] = c[nt][3];
        }
    }
}

template <int KIN, int LDA, bool BIAS, bool GLOBAL>
__device__ __forceinline__ void mma_gemm16(
    const float* __restrict__ A_s, const uint4* __restrict__ Bpk,
    const float* __restrict__ bias, float* __restrict__ C, int row0)
{
    float c[4][4];
    mma_core<KIN, LDA, BIAS>(A_s, Bpk, bias, c);
    frag_store<GLOBAL>(c, C, row0);
}

// edge first layer (dual tile): edge-feat GEMM + bias + Hd[dst] + Hs[src] -> hid_s (32 rows)
__device__ __forceinline__ void mma_edge_l1_dual(
    const float* __restrict__ A_s, const uint4* __restrict__ Bpk,
    const float* __restrict__ b1,
    const float* __restrict__ Hd, const float* __restrict__ Hs,
    const int* __restrict__ dst_s, const int* __restrict__ src_s,
    float* __restrict__ hid_s)
{
    const int lane = threadIdx.x & 31;
    const int warp = threadIdx.x >> 5;
    const int g = lane >> 2, tig = lane & 3;
    const int n0 = warp * 32;
    float c0[4][4], c1[4][4];
#pragma unroll
    for (int nt = 0; nt < 4; nt++) {
        const int ce = n0 + nt * 8 + 2 * tig;
        const float2 bd = *(const float2*)(b1 + ce);
        {
            const float2 d0 = *(const float2*)(Hd + dst_s[g] * 128 + ce);
            const float2 s0 = *(const float2*)(Hs + src_s[g] * 128 + ce);
            const float2 d8 = *(const float2*)(Hd + dst_s[g + 8] * 128 + ce);
            const float2 s8 = *(const float2*)(Hs + src_s[g + 8] * 128 + ce);
            c0[nt][0] = bd.x + d0.x + s0.x;
            c0[nt][1] = bd.y + d0.y + s0.y;
            c0[nt][2] = bd.x + d8.x + s8.x;
            c0[nt][3] = bd.y + d8.y + s8.y;
        }
        {
            const float2 d0 = *(const float2*)(Hd + dst_s[16 + g] * 128 + ce);
            const float2 s0 = *(const float2*)(Hs + src_s[16 + g] * 128 + ce);
            const float2 d8 = *(const float2*)(Hd + dst_s[24 + g] * 128 + ce);
            const float2 s8 = *(const float2*)(Hs + src_s[24 + g] * 128 + ce);
            c1[nt][0] = bd.x + d0.x + s0.x;
            c1[nt][1] = bd.y + d0.y + s0.y;
            c1[nt][2] = bd.x + d8.x + s8.x;
            c1[nt][3] = bd.y + d8.y + s8.y;
        }
    }
#pragma unroll
    for (int k = 0; k < 32; k += 16) {
        const AFrag f0 = load_afrag<LDE>(A_s, k, g, tig);
        const AFrag f1 = load_afrag<LDE>(A_s + 16 * LDE, k, g, tig);
        const int kbase = (k >> 4) * 128;
#pragma unroll
        for (int nt = 0; nt < 4; nt++) {
            const int nc = n0 + nt * 8 + g;
            const uint4 b = Bpk[(kbase + nc) * 4 + tig];
            mma3(c0[nt], f0, b);
            mma3(c1[nt], f1, b);
        }
    }
    frag_store<false>(c0, hid_s, 0);
    frag_store<false>(c1, hid_s, 16);
}

// ---------------- LN(+affine)+ReLU over ROWS rows (stride LDH) ----------------
template <int ROWS>
__device__ __forceinline__ void ln_relu(float* hid_s, float* mu_s, float* rs_s,
                                        const float* __restrict__ gam,
                                        const float* __restrict__ bet) {
    const int t = threadIdx.x;
    const int w = t >> 5, lane = t & 31;
    __syncthreads();
    for (int e = w; e < ROWS; e += 4) {
        float s = 0.f, s2 = 0.f;
#pragma unroll
        for (int j = 0; j < 4; j++) {
            const float v = hid_s[e * LDH + lane + j * 32];
            s += v; s2 += v * v;
        }
#pragma unroll
        for (int o = 16; o; o >>= 1) {
            s  += __shfl_down_sync(0xffffffffu, s, o);
            s2 += __shfl_down_sync(0xffffffffu, s2, o);
        }
        if (lane == 0) {
            const float mu = s * (1.f / 128.f);
            const float var = s2 * (1.f / 128.f) - mu * mu;
            mu_s[e] = mu;
            rs_s[e] = rsqrtf(var + 1e-5f);
        }
    }
    __syncthreads();
    const float gt = gam[t], bt = bet[t];
#pragma unroll
    for (int e = 0; e < ROWS; e++) {
        float v = hid_s[e * LDH + t];
        v = fmaf((v - mu_s[e]) * rs_s[e], gt, bt);
        hid_s[e * LDH + t] = fmaxf(v, 0.f);
    }
    __syncthreads();
}

// ---------------- kernels ----------------
__global__ void init_kernel(int n) {
    const int i = blockIdx.x * blockDim.x + threadIdx.x;
    if (i < n * 128) g_attn[i] = 0.f;
    if (i < n * 16) { g_mx[i] = __int_as_float(0xff800000); g_den[i] = 0.f; }
}

__global__ void split_kernel(const float* qW1, const float* qW2,
                             const float* kW1, const float* kW2,
                             const float* vW1, const float* vW2,
                             const float* oW1, const float* oW2) {
    const int m = blockIdx.y;
    const float* src; int dst, K, Klim;
    switch (m) {
        case 0:  src = qW1;             dst = P_QW1;  K = 128; Klim = 128; break;
        case 1:  src = qW2;             dst = P_QW2;  K = 128; Klim = 128; break;
        case 2:  src = kW1 + 24 * 128;  dst = P_KW1D; K = 128; Klim = 128; break;
        case 3:  src = kW1 + 152 * 128; dst = P_KW1S; K = 128; Klim = 128; break;
        case 4:  src = vW1 + 24 * 128;  dst = P_VW1D; K = 128; Klim = 128; break;
        case 5:  src = vW1 + 152 * 128; dst = P_VW1S; K = 128; Klim = 128; break;
        case 6:  src = kW2;             dst = P_KW2;  K = 128; Klim = 128; break;
        case 7:  src = vW2;             dst = P_VW2;  K = 128; Klim = 128; break;
        case 8:  src = oW1;             dst = P_OW1;  K = 256; Klim = 256; break;
        case 9:  src = oW2;             dst = P_OW2;  K = 128; Klim = 128; break;
        case 10: src = kW1;             dst = P_KW1A; K = 32;  Klim = 24;  break;
        default: src = vW1;             dst = P_VW1A; K = 32;  Klim = 24;  break;
    }
    const int cnt = (K >> 4) * 128 * 4;
    for (int i = blockIdx.x * blockDim.x + threadIdx.x; i < cnt;
         i += gridDim.x * blockDim.x) {
        const int tig = i & 3;
        const int nc  = (i >> 2) & 127;
        const int k16 = i >> 9;
        const int r0 = k16 * 16 + 2 * tig;
        float2 x0, x1;
        x0.x = (r0     < Klim) ? src[(r0    ) * 128 + nc] : 0.f;
        x0.y = (r0 + 1 < Klim) ? src[(r0 + 1) * 128 + nc] : 0.f;
        x1.x = (r0 + 8 < Klim) ? src[(r0 + 8) * 128 + nc] : 0.f;
        x1.y = (r0 + 9 < Klim) ? src[(r0 + 9) * 128 + nc] : 0.f;
        uint4 b;
        b.x = pk_bf16x2(x0.x, x0.y);
        b.y = pk_bf16x2(x1.x, x1.y);
        b.z = pk_residual(x0, b.x);
        b.w = pk_residual(x1, b.y);
        g_wpk[dst + i] = b;
    }
}

__global__ void __launch_bounds__(NTHREADS)
nodeprep_kernel(const float* __restrict__ h, int n,
                const float* qb1, const float* qg, const float* qbe,
                const float* qb2) {
    __shared__ __align__(16) float in_s[TILE * LDH];
    __shared__ __align__(16) float hid_s[TILE * LDH];
    __shared__ float mu_s[TILE], rs_s[TILE];
    const int t = threadIdx.x;
    const int n0 = blockIdx.x * TILE;
    for (int e = 0; e < TILE; e++) in_s[e * LDH + t] = h[(n0 + e) * 128 + t];
    __syncthreads();

    mma_gemm16<128, LDH, true, false>(in_s, g_wpk + P_QW1, qb1, hid_s, 0);
    ln_relu<TILE>(hid_s, mu_s, rs_s, qg, qbe);
    mma_gemm16<128, LDH, true, true>(hid_s, g_wpk + P_QW2, qb2, g_q, n0);
    mma_gemm16<128, LDH, false, true>(in_s, g_wpk + P_KW1D, (const float*)0, g_kHd, n0);
    mma_gemm16<128, LDH, false, true>(in_s, g_wpk + P_KW1S, (const float*)0, g_kHs, n0);
    mma_gemm16<128, LDH, false, true>(in_s, g_wpk + P_VW1D, (const float*)0, g_vHd, n0);
    mma_gemm16<128, LDH, false, true>(in_s, g_wpk + P_VW1S, (const float*)0, g_vHs, n0);
}

// edge pass A (32 edges/block): all-MMA k-MLP; scores straight from fragments
__global__ void __launch_bounds__(NTHREADS)
edgeA_kernel(const float* __restrict__ rf, const float* __restrict__ ef,
             const int* __restrict__ srcI, const int* __restrict__ dstI, int Ecnt,
             const float* kb1, const float* kg, const float* kbe,
             const float* kb2) {
    __shared__ __align__(16) float sm_in[TE * LDE];
    __shared__ __align__(16) float hid_s[TE * LDH];
    __shared__ float mu_s[TE], rs_s[TE];
    __shared__ int dst_s[TE], src_s[TE];
    const int t = threadIdx.x;
    const int e0 = blockIdx.x * TE;
    const int ne = min(TE, Ecnt - e0);

    if (t < TE) {
        int idx = e0 + t; if (idx >= Ecnt) idx = Ecnt - 1;
        dst_s[t] = dstI[idx]; src_s[t] = srcI[idx];
    }
    for (int j = t; j < TE * 8; j += NTHREADS)
        sm_in[(j >> 3) * LDE + 24 + (j & 7)] = 0.f;
    for (int j = t; j < ne * 24; j += NTHREADS) {
        const int e = j / 24, i = j % 24;
        sm_in[e * LDE + i] = (i < 4) ? ef[(e0 + e) * 4 + i] : rf[(e0 + e) * 20 + (i - 4)];
    }
    __syncthreads();

    mma_edge_l1_dual(sm_in, g_wpk + P_KW1A, kb1, g_kHd, g_kHs, dst_s, src_s, hid_s);
    ln_relu<TE>(hid_s, mu_s, rs_s, kg, kbe);
    float c0[4][4], c1[4][4];
    mma_core_dual<128, LDH, true>(hid_s, g_wpk + P_KW2, kb2, c0, c1);

    // score epilogue straight from fragments (both tiles)
    const int lane = t & 31, warp = t >> 5;
    const int g = lane >> 2, tig = lane & 3;
    const int n0 = warp * 32;
#pragma unroll
    for (int tt = 0; tt < 2; tt++) {
        const int r = tt * 16;
        float (*cc)[4] = tt ? c1 : c0;
#pragma unroll
        for (int nt = 0; nt < 4; nt++) {
            const int ce = n0 + nt * 8 + 2 * tig;
            const float2 qa = *(const float2*)(g_q + dst_s[r + g] * 128 + ce);
            const float2 qb = *(const float2*)(g_q + dst_s[r + g + 8] * 128 + ce);
            float p0 = cc[nt][0] * qa.x + cc[nt][1] * qa.y;
            float p8 = cc[nt][2] * qb.x + cc[nt][3] * qb.y;
            p0 += __shfl_xor_sync(0xffffffffu, p0, 1);
            p0 += __shfl_xor_sync(0xffffffffu, p0, 2);
            p8 += __shfl_xor_sync(0xffffffffu, p8, 1);
            p8 += __shfl_xor_sync(0xffffffffu, p8, 2);
            if (tig == 0) {
                const int hh = warp * 4 + nt;
                if (e0 + r + g < Ecnt) {
                    const float sc = p0 * 0.35355339059327373f; // 1/sqrt(8)
                    g_scores[(e0 + r + g) * 16 + hh] = sc;
                    atomicMaxF(&g_mx[dst_s[r + g] * 16 + hh], sc);
                }
                if (e0 + r + g + 8 < Ecnt) {
                    const float sc = p8 * 0.35355339059327373f;
                    g_scores[(e0 + r + g + 8) * 16 + hh] = sc;
                    atomicMaxF(&g_mx[dst_s[r + g + 8] * 16 + hh], sc);
                }
            }
        }
    }
}

__global__ void softmax_kernel(const int* __restrict__ dstI, int Ecnt) {
    const int gid = blockIdx.x * blockDim.x + threadIdx.x;
    if (gid >= Ecnt * 16) return;
    const int e = gid >> 4, hh = gid & 15;
    const int node = dstI[e];
    const float exv = expf(g_scores[gid] - g_mx[node * 16 + hh]);
    g_scores[gid] = exv;
    atomicAdd(&g_den[node * 16 + hh], exv);
}

// edge pass B (32 edges/block): all-MMA v-MLP; alpha*v scattered from fragments
__global__ void __launch_bounds__(NTHREADS)
edgeB_kernel(const float* __restrict__ rf, const float* __restrict__ ef,
             const float* __restrict__ ew,
             const int* __restrict__ srcI, const int* __restrict__ dstI, int Ecnt,
             const float* vb1, const float* vg, const float* vbe,
             const float* vb2) {
    __shared__ __align__(16) float sm_in[TE * LDE];
    __shared__ __align__(16) float hid_s[TE * LDH];
    __shared__ float mu_s[TE], rs_s[TE], ew_s[TE];
    __shared__ float alpha_s[TE * 16];
    __shared__ int dst_s[TE], src_s[TE];
    const int t = threadIdx.x;
    const int e0 = blockIdx.x * TE;
    const int ne = min(TE, Ecnt - e0);

    if (t < TE) {
        int idx = e0 + t; if (idx >= Ecnt) idx = Ecnt - 1;
        dst_s[t] = dstI[idx]; src_s[t] = srcI[idx];
        ew_s[t] = ew[idx];
    }
    for (int j = t; j < TE * 8; j += NTHREADS)
        sm_in[(j >> 3) * LDE + 24 + (j & 7)] = 0.f;
    for (int j = t; j < ne * 24; j += NTHREADS) {
        const int e = j / 24, i = j % 24;
        sm_in[e * LDE + i] = (i < 4) ? ef[(e0 + e) * 4 + i] : rf[(e0 + e) * 20 + (i - 4)];
    }
    __syncthreads();

    // alpha (incl. e_w); visible to epilogue via ln_relu's barriers
    for (int j = t; j < ne * 16; j += NTHREADS) {
        const int e = j >> 4, hh = j & 15;
        alpha_s[j] = g_scores[(e0 + e) * 16 + hh] / g_den[dst_s[e] * 16 + hh] * ew_s[e];
    }

    mma_edge_l1_dual(sm_in, g_wpk + P_VW1A, vb1, g_vHd, g_vHs, dst_s, src_s, hid_s);
    ln_relu<TE>(hid_s, mu_s, rs_s, vg, vbe);
    float c0[4][4], c1[4][4];
    mma_core_dual<128, LDH, true>(hid_s, g_wpk + P_VW2, vb2, c0, c1);

    // scatter epilogue straight from fragments (both tiles)
    const int lane = t & 31, warp = t >> 5;
    const int g = lane >> 2, tig = lane & 3;
    const int n0 = warp * 32;
#pragma unroll
    for (int tt = 0; tt < 2; tt++) {
        const int r = tt * 16;
        float (*cc)[4] = tt ? c1 : c0;
#pragma unroll
        for (int nt = 0; nt < 4; nt++) {
            const int hh = warp * 4 + nt;
            const int ce = n0 + nt * 8 + 2 * tig;
            if (e0 + r + g < Ecnt) {
                const float a = alpha_s[(r + g) * 16 + hh];
                red_add_v2(&g_attn[dst_s[r + g] * 128 + ce], cc[nt][0] * a, cc[nt][1] * a);
            }
            if (e0 + r + g + 8 < Ecnt) {
                const float a = alpha_s[(r + g + 8) * 16 + hh];
                red_add_v2(&g_attn[dst_s[r + g + 8] * 128 + ce], cc[nt][2] * a, cc[nt][3] * a);
            }
        }
    }
}

__global__ void __launch_bounds__(NTHREADS)
out_kernel(const float* __restrict__ h, float* __restrict__ outp, int n,
           const float* b1, const float* gam, const float* bet,
           const float* b2) {
    __shared__ __align__(16) float in_s[TILE * LDO];
    __shared__ __align__(16) float hid_s[TILE * LDH];
    __shared__ float mu_s[TILE], rs_s[TILE];
    const int t = threadIdx.x;
    const int n0 = blockIdx.x * TILE;
    for (int e = 0; e < TILE; e++) {
        const int node = n0 + e;
        in_s[e * LDO + t] = g_attn[node * 128 + t];
        in_s[e * LDO + 128 + t] = h[node * 128 + t];
    }
    __syncthreads();
    mma_gemm16<256, LDO, true, false>(in_s, g_wpk + P_OW1, b1, hid_s, 0);
    ln_relu<TILE>(hid_s, mu_s, rs_s, gam, bet);
    mma_gemm16<128, LDH, true, true>(hid_s, g_wpk + P_OW2, b2, outp, n0);
}

// ---------------- launch ----------------
extern "C" void kernel_launch(void* const* d_in, const int* in_sizes, int n_in,
                              void* d_out, int out_size) {
    int ih = -1, ir = -1, ief = -1, iei = -1, iew = -1, xk0 = -1;
    for (int i = 0; i < n_in; i++) {
        switch (in_sizes[i]) {
            case 6400000:  if (ih  < 0) ih  = i; break; // h [N,128]
            case 12000000: if (ir  < 0) ir  = i; break; // r_feat [E,20]
            case 2400000:  if (ief < 0) ief = i; break; // edge_feat [E,4]
            case 1200000:  if (iei < 0) iei = i; break; // edge_index [2,E]
            case 600000:   if (iew < 0) iew = i; break; // e_w [E]
            case 35840:    if (xk0 < 0) xk0 = i; break; // xk_W1 [280,128] (first)
            default: break;
        }
    }
    const int xv0 = xk0 + 6, xq0 = xk0 + 12, o0 = xk0 + 18;

    const float* h   = (const float*)d_in[ih];
    const float* rf  = (const float*)d_in[ir];
    const float* ef  = (const float*)d_in[ief];
    const float* ew  = (const float*)d_in[iew];
    const int*   ei  = (const int*)d_in[iei];
    const int N = in_sizes[ih] / 128;
    const int E = in_sizes[iew];
    const int* srcI = ei;
    const int* dstI = ei + E;

#define G(base, off) ((const float*)d_in[(base) + (off)])
    float* outp = (float*)d_out;

    init_kernel<<<(N * 128 + 255) / 256, 256>>>(N);
    {
        dim3 grid(32, 12);
        split_kernel<<<grid, 256>>>(G(xq0,0), G(xq0,4), G(xk0,0), G(xk0,4),
                                    G(xv0,0), G(xv0,4), G(o0,0),  G(o0,4));
    }
    nodeprep_kernel<<<(N + TILE - 1) / TILE, NTHREADS>>>(
        h, N, G(xq0,1), G(xq0,2), G(xq0,3), G(xq0,5));
    edgeA_kernel<<<(E + TE - 1) / TE, NTHREADS>>>(
        rf, ef, srcI, dstI, E,
        G(xk0,1), G(xk0,2), G(xk0,3), G(xk0,5));
    softmax_kernel<<<(E * 16 + 255) / 256, 256>>>(dstI, E);
    edgeB_kernel<<<(E + TE - 1) / TE, NTHREADS>>>(
        rf, ef, ew, srcI, dstI, E,
        G(xv0,1), G(xv0,2), G(xv0,3), G(xv0,5));
    out_kernel<<<(N + TILE - 1) / TILE, NTHREADS>>>(
        h, outp, N, G(o0,1), G(o0,2), G(o0,3), G(o0,5));
#undef G
}